// round 15
// baseline (speedup 1.0000x reference)
#include <cuda_runtime.h>
#include <cuda_fp16.h>
#include <cuda_bf16.h>
#include <math.h>
#include <stdint.h>

// ---------------- problem constants ----------------
#define Vv 32000
#define Dd 1024
#define NLAYER 4
#define ED 2048
#define Nn 16
#define DR 64
#define DCONV 4
#define Bb 2
#define Ll 1024
#define Mm (Bb * Ll)      // 2048 tokens
#define HM Ll             // tokens per sequence (1024)
#define DX (DR + 2 * Nn)  // 96
#define CHUNKS 32
#define CLEN (Ll / CHUNKS)   // 32
#define NCH (Bb * ED)        // 4096 channels
#define XPSPLIT 8            // split-K factor for x_proj

// per-layer weight element counts
#define IN_L ((size_t)2 * ED * Dd)
#define DT_L ((size_t)ED * DR)
#define OUT_L ((size_t)Dd * ED)

// ---------------- scratch (no allocs allowed) ----------------
__device__ __align__(256) float g_x[Mm * Dd];
__device__ __align__(256) float g_delta[Mm * ED];
__device__ __align__(256) float g_dbc[Mm * DX];
__device__ __align__(256) float g_xp_part[Bb * XPSPLIT * HM * 128];   // split-K partials
// chunked-scan state: [b][e][chunk][n]
__device__ __align__(256) float g_A[NCH * CHUNKS * Nn];
__device__ __align__(256) float g_hl[NCH * CHUNKS * Nn];
__device__ __align__(256) float g_hs[NCH * CHUNKS * Nn];

// fp16 activation / weight mirrors (zero-initialized; x_proj pad rows stay 0)
__device__ __align__(256) __half h_xz[Mm * 2 * ED];
__device__ __align__(256) __half h_xn[Mm * Dd];
__device__ __align__(256) __half h_xs[Mm * ED];
__device__ __align__(256) __half h_dr[Mm * DR];
__device__ __align__(256) __half h_y[Mm * ED];
__device__ __align__(256) __half h_w_in[NLAYER * 2 * ED * Dd];
__device__ __align__(256) __half h_w_xp[NLAYER * 128 * ED];   // padded 96->128 rows
__device__ __align__(256) __half h_w_dt[NLAYER * ED * DR];
__device__ __align__(256) __half h_w_out[NLAYER * Dd * ED];
__device__ __align__(256) __half h_emb[Vv * Dd];

// ================= small PTX helpers =================
__device__ __forceinline__ uint32_t smem_u32(const void* p) {
    uint32_t a;
    asm("{ .reg .u64 t; cvta.to.shared.u64 t, %1; cvt.u32.u64 %0, t; }" : "=r"(a) : "l"(p));
    return a;
}
__device__ __forceinline__ void ldsm_x4(uint32_t* r, uint32_t addr) {
    asm volatile("ldmatrix.sync.aligned.m8n8.x4.shared.b16 {%0,%1,%2,%3}, [%4];"
                 : "=r"(r[0]), "=r"(r[1]), "=r"(r[2]), "=r"(r[3]) : "r"(addr));
}
__device__ __forceinline__ void mma16816(float* d, const uint32_t* a, uint32_t b0, uint32_t b1) {
    asm volatile("mma.sync.aligned.m16n8k16.row.col.f32.f16.f16.f32 "
                 "{%0,%1,%2,%3}, {%4,%5,%6,%7}, {%8,%9}, {%0,%1,%2,%3};"
                 : "+f"(d[0]), "+f"(d[1]), "+f"(d[2]), "+f"(d[3])
                 : "r"(a[0]), "r"(a[1]), "r"(a[2]), "r"(a[3]), "r"(b0), "r"(b1));
}
#define CP_ASYNC16(dst, src) \
    asm volatile("cp.async.cg.shared.global [%0], [%1], 16;" :: "r"(dst), "l"(src))
#define CP_COMMIT() asm volatile("cp.async.commit_group;" ::: "memory")
#define CP_WAIT1()  asm volatile("cp.async.wait_group 1;" ::: "memory")

// ================= HMMA fp16 GEMM: C(M,N) = A(M,K) @ B(N,K)^T =================
// EPI: 0 store fp32, 1 accumulate fp32 (residual), 2 softplus(acc+bias) fp32,
//      4 store fp16 (C reinterpreted as __half*)
#define BMt 128
#define BNt 128
#define BKt 64
#define STAGES 3
#define ASTRIDE 72
#define TILE_HALFS (128 * ASTRIDE)
#define STAGE_BYTES (2 * TILE_HALFS * 2)
#define GEMM_SMEM (STAGES * STAGE_BYTES)
#define GTHREADS 512

__device__ __forceinline__ void gemm_load_stage(uint32_t sbase, int s,
                                                const __half* A, int lda,
                                                const __half* Bw, int ldb,
                                                int m0, int n0, int c, int tid) {
    uint32_t sa = sbase + s * STAGE_BYTES;
    uint32_t sb = sa + TILE_HALFS * 2;
    const __half* Ap = A + (size_t)m0 * lda + c * BKt;
    const __half* Bp = Bw + (size_t)n0 * ldb + c * BKt;
    int row = tid >> 3, slot = tid & 7;
#pragma unroll
    for (int i = 0; i < 2; i++) {
        int r = row + i * 64;
        CP_ASYNC16(sa + (r * ASTRIDE + slot * 8) * 2, Ap + (size_t)r * lda + slot * 8);
        CP_ASYNC16(sb + (r * ASTRIDE + slot * 8) * 2, Bp + (size_t)r * ldb + slot * 8);
    }
}

template <int EPI>
__global__ void __launch_bounds__(GTHREADS, 1) hgemm_mma(const __half* __restrict__ A, int lda,
                                                         const __half* __restrict__ Bw, int ldb,
                                                         float* __restrict__ C, int ldc,
                                                         int M, int N, int Nstore, int K,
                                                         const float* __restrict__ bias,
                                                         size_t zstrC) {
    extern __shared__ __half sh[];
    uint32_t sbase = smem_u32(sh);
    int tid = threadIdx.x;
    int wid = tid >> 5, lane = tid & 31;
    int warp_m = wid >> 2, warp_n = wid & 3;
    int m0 = blockIdx.y * BMt, n0 = blockIdx.x * BNt;
    int kz = blockIdx.z;
    A += (size_t)kz * K;
    Bw += (size_t)kz * K;
    C += (size_t)kz * zstrC;
    int KC = K / BKt;

    float acc[2][4][4];
#pragma unroll
    for (int i = 0; i < 2; i++)
#pragma unroll
        for (int j = 0; j < 4; j++)
#pragma unroll
            for (int k = 0; k < 4; k++) acc[i][j][k] = 0.f;

#pragma unroll
    for (int s = 0; s < STAGES - 1; s++) {
        if (s < KC) gemm_load_stage(sbase, s, A, lda, Bw, ldb, m0, n0, s, tid);
        CP_COMMIT();
    }

    int lrow = lane & 15;
    int kcol8 = (lane >> 4) * 8;
    uint32_t afr[2][2][4], bfr[2][2][4];

    for (int c = 0; c < KC; c++) {
        CP_WAIT1();
        __syncthreads();

        int cn = c + STAGES - 1;
        if (cn < KC)
            gemm_load_stage(sbase, cn % STAGES, A, lda, Bw, ldb, m0, n0, cn, tid);
        CP_COMMIT();

        uint32_t sa = sbase + (c % STAGES) * STAGE_BYTES;
        uint32_t sb = sa + TILE_HALFS * 2;

#pragma unroll
        for (int mf = 0; mf < 2; mf++)
            ldsm_x4(afr[0][mf], sa + ((warp_m * 32 + mf * 16 + lrow) * ASTRIDE + kcol8) * 2);
#pragma unroll
        for (int nh = 0; nh < 2; nh++)
            ldsm_x4(bfr[0][nh], sb + ((warp_n * 32 + nh * 16 + lrow) * ASTRIDE + kcol8) * 2);

#pragma unroll
        for (int kk = 0; kk < 4; kk++) {
            int b = kk & 1;
            if (kk < 3) {
                int kof = (kk + 1) * 16 + kcol8;
#pragma unroll
                for (int mf = 0; mf < 2; mf++)
                    ldsm_x4(afr[b ^ 1][mf], sa + ((warp_m * 32 + mf * 16 + lrow) * ASTRIDE + kof) * 2);
#pragma unroll
                for (int nh = 0; nh < 2; nh++)
                    ldsm_x4(bfr[b ^ 1][nh], sb + ((warp_n * 32 + nh * 16 + lrow) * ASTRIDE + kof) * 2);
            }
#pragma unroll
            for (int mf = 0; mf < 2; mf++)
#pragma unroll
                for (int nf = 0; nf < 4; nf++) {
                    int nh = nf >> 1, odd = nf & 1;
                    mma16816(acc[mf][nf], afr[b][mf], bfr[b][nh][odd], bfr[b][nh][odd + 2]);
                }
        }
    }

    int g = lane >> 2, t4 = lane & 3;
#pragma unroll
    for (int mf = 0; mf < 2; mf++) {
        int row0 = m0 + warp_m * 32 + mf * 16 + g;
#pragma unroll
        for (int nf = 0; nf < 4; nf++) {
            int n = n0 + warp_n * 32 + nf * 8 + 2 * t4;
            if (n >= Nstore) continue;
            float2 v0 = make_float2(acc[mf][nf][0], acc[mf][nf][1]);
            float2 v1 = make_float2(acc[mf][nf][2], acc[mf][nf][3]);
            if (EPI == 4) {
                __half* Ch = (__half*)C;
                *(__half2*)(Ch + (size_t)row0 * ldc + n) = __floats2half2_rn(v0.x, v0.y);
                *(__half2*)(Ch + (size_t)(row0 + 8) * ldc + n) = __floats2half2_rn(v1.x, v1.y);
                continue;
            }
            float* C0 = C + (size_t)row0 * ldc;
            float* C1 = C0 + (size_t)8 * ldc;
            if (EPI == 1) {
                float2 o0 = *(float2*)(C0 + n);
                float2 o1 = *(float2*)(C1 + n);
                v0.x += o0.x; v0.y += o0.y;
                v1.x += o1.x; v1.y += o1.y;
            }
            if (EPI == 2) {
                float b0 = bias[n], b1 = bias[n + 1];
                v0.x += b0; v0.y += b1; v1.x += b0; v1.y += b1;
                v0.x = (v0.x > 20.f) ? v0.x : __logf(1.f + __expf(v0.x));
                v0.y = (v0.y > 20.f) ? v0.y : __logf(1.f + __expf(v0.y));
                v1.x = (v1.x > 20.f) ? v1.x : __logf(1.f + __expf(v1.x));
                v1.y = (v1.y > 20.f) ? v1.y : __logf(1.f + __expf(v1.y));
            }
            *(float2*)(C0 + n) = v0;
            *(float2*)(C1 + n) = v1;
        }
    }
}

// split-K reduce (per sequence, float4-vectorized): dbc (fp32) + delta_r (fp16)
__global__ void __launch_bounds__(256) xp_reduce(const float* __restrict__ part,
                                                 float* __restrict__ dbc,
                                                 __half* __restrict__ dr16) {
    int i = blockIdx.x * 256 + threadIdx.x;   // over HM*128/4 vec4 units
    if (i >= HM * 128 / 4) return;
    int m = i >> 5;            // 32 vec4 per row
    int col = (i & 31) * 4;
    float4 s = ((const float4*)part)[i];
#pragma unroll
    for (int z = 1; z < XPSPLIT; z++) {
        float4 v = ((const float4*)(part + (size_t)z * (HM * 128)))[i];
        s.x += v.x; s.y += v.y; s.z += v.z; s.w += v.w;
    }
    if (col < DX) *(float4*)(dbc + m * DX + col) = s;
    if (col < DR) {
        __half2 a = __floats2half2_rn(s.x, s.y);
        __half2 b = __floats2half2_rn(s.z, s.w);
        uint32_t pa = *(uint32_t*)&a, pb = *(uint32_t*)&b;
        uint2 o = make_uint2(pa, pb);
        *(uint2*)(dr16 + m * DR + col) = o;
    }
}

// ================= conversion kernels =================
__device__ __forceinline__ void cvt8(const float4* sp, uint4* dp) {
    float4 a = sp[0], b = sp[1];
    __half2 h0 = __floats2half2_rn(a.x, a.y);
    __half2 h1 = __floats2half2_rn(a.z, a.w);
    __half2 h2 = __floats2half2_rn(b.x, b.y);
    __half2 h3 = __floats2half2_rn(b.z, b.w);
    uint4 o;
    o.x = *(uint32_t*)&h0; o.y = *(uint32_t*)&h1;
    o.z = *(uint32_t*)&h2; o.w = *(uint32_t*)&h3;
    *dp = o;
}

__global__ void __launch_bounds__(256) f16cvt(const float* __restrict__ s,
                                              __half* __restrict__ d, int n8) {
    int i = blockIdx.x * 256 + threadIdx.x;
    if (i >= n8) return;
    cvt8((const float4*)s + 2 * i, (uint4*)d + i);
}

__global__ void __launch_bounds__(256) xpw_to_f16_v8(const float* __restrict__ s,
                                                     __half* __restrict__ d) {
    int i = blockIdx.x * 256 + threadIdx.x;
    if (i >= NLAYER * DX * ED / 8) return;
    int l = i / (DX * ED / 8);
    int rem = i % (DX * ED / 8);
    int r = rem / (ED / 8);
    int cv = rem % (ED / 8);
    cvt8((const float4*)(s + ((size_t)(l * DX + r) * ED)) + 2 * cv,
         (uint4*)(d + ((size_t)l * 128 + r) * ED) + cv);
}

__global__ void __launch_bounds__(256) embed_kernel(const int* __restrict__ tok,
                                                    const float* __restrict__ emb,
                                                    float* __restrict__ out) {
    int idx = blockIdx.x * 256 + threadIdx.x;
    int m = idx >> 8;
    int d4 = idx & 255;
    ((float4*)out)[idx] = ((const float4*)(emb + (size_t)tok[m] * Dd))[d4];
}

__global__ void __launch_bounds__(256) rmsnorm_kernel(const float* __restrict__ x,
                                                      const float* __restrict__ w,
                                                      __half* __restrict__ out) {
    int row = blockIdx.x;
    const float* xr = x + (size_t)row * Dd;
    float v[4];
    float s = 0.f;
#pragma unroll
    for (int i = 0; i < 4; i++) {
        v[i] = xr[threadIdx.x + i * 256];
        s += v[i] * v[i];
    }
#pragma unroll
    for (int o = 16; o; o >>= 1) s += __shfl_xor_sync(0xffffffffu, s, o);
    __shared__ float ss[8];
    if ((threadIdx.x & 31) == 0) ss[threadIdx.x >> 5] = s;
    __syncthreads();
    if (threadIdx.x < 32) {
        float t = (threadIdx.x < 8) ? ss[threadIdx.x] : 0.f;
#pragma unroll
        for (int o = 4; o; o >>= 1) t += __shfl_xor_sync(0xffffffffu, t, o);
        if (threadIdx.x == 0) ss[0] = t;
    }
    __syncthreads();
    float r = rsqrtf(ss[0] * (1.f / (float)Dd) + 1e-5f);
    __half* orow = out + (size_t)row * Dd;
#pragma unroll
    for (int i = 0; i < 4; i++) {
        int d = threadIdx.x + i * 256;
        orow[d] = __float2half(v[i] * r * w[d]);
    }
}

// depthwise causal conv + bias + silu (per sequence)
__global__ void __launch_bounds__(256) conv_silu_kernel(const __half* __restrict__ xz,
                                                        const float* __restrict__ cw,
                                                        const float* __restrict__ cb,
                                                        __half* __restrict__ xs16) {
    int idx = blockIdx.x * 256 + threadIdx.x;   // over HM*ED/2
    int e2 = idx & (ED / 2 - 1);
    int e = e2 * 2;
    int m = idx >> 10;
    int l = m & (Ll - 1);
    const __half* xin = xz + (size_t)m * (2 * ED) + e;
    float4 wa = *(const float4*)(cw + e * 4);
    float4 wb = *(const float4*)(cw + e * 4 + 4);
    float2 cbv = *(const float2*)(cb + e);
    float2 x0 = __half22float2(*(const __half2*)xin);
    float a0 = cbv.x + wa.w * x0.x;
    float a1 = cbv.y + wb.w * x0.y;
    if (l >= 1) {
        float2 x1 = __half22float2(*(const __half2*)(xin - 2 * ED));
        a0 += wa.z * x1.x; a1 += wb.z * x1.y;
    }
    if (l >= 2) {
        float2 x2 = __half22float2(*(const __half2*)(xin - 4 * ED));
        a0 += wa.y * x2.x; a1 += wb.y * x2.y;
    }
    if (l >= 3) {
        float2 x3 = __half22float2(*(const __half2*)(xin - 6 * ED));
        a0 += wa.x * x3.x; a1 += wb.x * x3.y;
    }
    float r0 = a0 / (1.f + __expf(-a0));
    float r1 = a1 / (1.f + __expf(-a1));
    *(__half2*)(xs16 + (size_t)m * ED + e) = __floats2half2_rn(r0, r1);
}

// ================= chunked selective scan (4 lanes x 4 states, 32 chunks) ========
__global__ void __launch_bounds__(256) scan_pass1(const float* __restrict__ delta,
                                                  const __half* __restrict__ xs,
                                                  const float* __restrict__ dbc,
                                                  const float* __restrict__ A_log,
                                                  int bsel) {
    int u = blockIdx.x * 64 + (threadIdx.x >> 2);   // 0 .. ED*CHUNKS-1
    int j = threadIdx.x & 3;                        // states 4j..4j+3
    int c = u >> 11;
    int e = u & (ED - 1);
    float4 al = *(const float4*)(A_log + e * Nn + 4 * j);
    float a0 = -__expf(al.x) * 1.44269504f;
    float a1 = -__expf(al.y) * 1.44269504f;
    float a2 = -__expf(al.z) * 1.44269504f;
    float a3 = -__expf(al.w) * 1.44269504f;
    size_t t0 = (size_t)bsel * Ll + c * CLEN;
    const float* pd = delta + t0 * ED + e;
    const __half* pxs = xs + t0 * ED + e;
    const float* pB = dbc + t0 * DX + DR + 4 * j;
    float h0 = 0.f, h1 = 0.f, h2 = 0.f, h3 = 0.f;
    float s0 = 0.f, s1 = 0.f, s2 = 0.f, s3 = 0.f;
#pragma unroll 4
    for (int t = 0; t < CLEN; t++) {
        float d = *pd;
        float xv = __half2float(*pxs);
        float4 Bv = *(const float4*)pB;
        float e0 = d * a0, e1 = d * a1, e2v = d * a2, e3 = d * a3;
        s0 += e0; s1 += e1; s2 += e2v; s3 += e3;
        float dx = d * xv;
        h0 = fmaf(exp2f(e0), h0, dx * Bv.x);
        h1 = fmaf(exp2f(e1), h1, dx * Bv.y);
        h2 = fmaf(exp2f(e2v), h2, dx * Bv.z);
        h3 = fmaf(exp2f(e3), h3, dx * Bv.w);
        pd += ED; pxs += ED; pB += DX;
    }
    int o = (((bsel * ED + e) * CHUNKS) + c) * Nn + 4 * j;
    *(float4*)(g_hl + o) = make_float4(h0, h1, h2, h3);
    *(float4*)(g_A + o) = make_float4(exp2f(s0), exp2f(s1), exp2f(s2), exp2f(s3));
}

// pass2: serial prefix over chunks -> start state per chunk (per sequence)
__global__ void __launch_bounds__(256) scan_pass2(int bsel) {
    int i = blockIdx.x * 256 + threadIdx.x;   // 0 .. ED*Nn-1
    int e = i >> 4, n = i & 15;
    int chb = (bsel * ED + e) * CHUNKS;
    float hs = 0.f;
#pragma unroll
    for (int c = 0; c < CHUNKS; c++) {
        int o = (chb + c) * Nn + n;
        g_hs[o] = hs;
        hs = fmaf(g_A[o], hs, g_hl[o]);
    }
}

__global__ void __launch_bounds__(256) scan_pass3(const float* __restrict__ delta,
                                                  const __half* __restrict__ xs,
                                                  const float* __restrict__ dbc,
                                                  const __half* __restrict__ xz,
                                                  const float* __restrict__ A_log,
                                                  const float* __restrict__ Dp,
                                                  __half* __restrict__ y,
                                                  int bsel) {
    int u = blockIdx.x * 64 + (threadIdx.x >> 2);
    int j = threadIdx.x & 3;
    int c = u >> 11;
    int e = u & (ED - 1);
    float4 al = *(const float4*)(A_log + e * Nn + 4 * j);
    float a0 = -__expf(al.x) * 1.44269504f;
    float a1 = -__expf(al.y) * 1.44269504f;
    float a2 = -__expf(al.z) * 1.44269504f;
    float a3 = -__expf(al.w) * 1.44269504f;
    float dpar = Dp[e];

    int o = (((bsel * ED + e) * CHUNKS) + c) * Nn + 4 * j;
    float4 Hs = *(const float4*)(g_hs + o);
    float h0 = Hs.x, h1 = Hs.y, h2 = Hs.z, h3 = Hs.w;

    size_t t0 = (size_t)bsel * Ll + c * CLEN;
    const float* pd = delta + t0 * ED + e;
    const __half* pxs = xs + t0 * ED + e;
    const float* pB = dbc + t0 * DX + DR + 4 * j;
    const float* pC = dbc + t0 * DX + DR + Nn + 4 * j;
    const __half* pz = xz + t0 * (2 * ED) + ED + e;
    __half* py = y + t0 * ED + e;

#pragma unroll 4
    for (int t = 0; t < CLEN; t++) {
        float d = *pd;
        float xv = __half2float(*pxs);
        float4 Bv = *(const float4*)pB;
        float4 Cv = *(const float4*)pC;
        float dx = d * xv;
        h0 = fmaf(exp2f(d * a0), h0, dx * Bv.x);
        h1 = fmaf(exp2f(d * a1), h1, dx * Bv.y);
        h2 = fmaf(exp2f(d * a2), h2, dx * Bv.z);
        h3 = fmaf(exp2f(d * a3), h3, dx * Bv.w);
        float p = h0 * Cv.x + h1 * Cv.y + h2 * Cv.z + h3 * Cv.w;
        p += __shfl_xor_sync(0xffffffffu, p, 1);
        p += __shfl_xor_sync(0xffffffffu, p, 2);
        if (j == 0) {
            float z = __half2float(*pz);
            float sz = z / (1.f + __expf(-z));
            py[0] = __float2half((p + dpar * xv) * sz);
        }
        pd += ED; pxs += ED; pB += DX; pC += DX; pz += 2 * ED; py += ED;
    }
}

// ---------------- host side ----------------
static void launch_hgemm(int epi, cudaStream_t st,
                         const __half* A, int lda, const __half* B, int ldb,
                         float* C, int ldc, int M, int N, int Nstore, int K,
                         const float* bias, int zsplit, size_t zstrC) {
    dim3 grid(N / BNt, M / BMt, zsplit);
    if (epi == 0)
        hgemm_mma<0><<<grid, GTHREADS, GEMM_SMEM, st>>>(A, lda, B, ldb, C, ldc, M, N, Nstore, K, bias, zstrC);
    else if (epi == 1)
        hgemm_mma<1><<<grid, GTHREADS, GEMM_SMEM, st>>>(A, lda, B, ldb, C, ldc, M, N, Nstore, K, bias, zstrC);
    else if (epi == 2)
        hgemm_mma<2><<<grid, GTHREADS, GEMM_SMEM, st>>>(A, lda, B, ldb, C, ldc, M, N, Nstore, K, bias, zstrC);
    else
        hgemm_mma<4><<<grid, GTHREADS, GEMM_SMEM, st>>>(A, lda, B, ldb, C, ldc, M, N, Nstore, K, bias, zstrC);
}

static void launch_cvt(const float* s, __half* d, size_t elems, cudaStream_t st) {
    int n8 = (int)(elems / 8);
    f16cvt<<<(n8 + 255) / 256, 256, 0, st>>>(s, d, n8);
}

extern "C" void kernel_launch(void* const* d_in, const int* in_sizes, int n_in,
                              void* d_out, int out_size) {
    const int* tokens = (const int*)d_in[0];
    const float* embedding = (const float*)d_in[1];
    const float* in_proj_w = (const float*)d_in[2];
    const float* conv_w = (const float*)d_in[3];
    const float* conv_b = (const float*)d_in[4];
    const float* x_proj_w = (const float*)d_in[5];
    const float* dt_proj_w = (const float*)d_in[6];
    const float* dt_proj_b = (const float*)d_in[7];
    const float* A_log = (const float*)d_in[8];
    const float* D_param = (const float*)d_in[9];
    const float* out_proj_w = (const float*)d_in[10];
    const float* norm_w = (const float*)d_in[11];
    const float* norm_f_w = (const float*)d_in[12];
    float* logits = (float*)d_out;

    float *px, *pdelta, *pdbc, *pxpp;
    __half *pxz16, *pxn16, *pxs16, *pdr16, *py16, *pwin, *pwxp, *pwdt, *pwout, *pemb;
    cudaGetSymbolAddress((void**)&px, g_x);
    cudaGetSymbolAddress((void**)&pdelta, g_delta);
    cudaGetSymbolAddress((void**)&pdbc, g_dbc);
    cudaGetSymbolAddress((void**)&pxpp, g_xp_part);
    cudaGetSymbolAddress((void**)&pxz16, h_xz);
    cudaGetSymbolAddress((void**)&pxn16, h_xn);
    cudaGetSymbolAddress((void**)&pxs16, h_xs);
    cudaGetSymbolAddress((void**)&pdr16, h_dr);
    cudaGetSymbolAddress((void**)&py16, h_y);
    cudaGetSymbolAddress((void**)&pwin, h_w_in);
    cudaGetSymbolAddress((void**)&pwxp, h_w_xp);
    cudaGetSymbolAddress((void**)&pwdt, h_w_dt);
    cudaGetSymbolAddress((void**)&pwout, h_w_out);
    cudaGetSymbolAddress((void**)&pemb, h_emb);

    // one-time smem attribute setup + side streams/events
    static cudaStream_t s2 = nullptr, s3 = nullptr;
    static cudaEvent_t evFork = nullptr, evJoin = nullptr, evEmb = nullptr, evW = nullptr;
    static cudaEvent_t evSkew = nullptr;
    static int sinit = 0;
    if (!sinit) {
        cudaFuncSetAttribute(hgemm_mma<0>, cudaFuncAttributeMaxDynamicSharedMemorySize, GEMM_SMEM);
        cudaFuncSetAttribute(hgemm_mma<1>, cudaFuncAttributeMaxDynamicSharedMemorySize, GEMM_SMEM);
        cudaFuncSetAttribute(hgemm_mma<2>, cudaFuncAttributeMaxDynamicSharedMemorySize, GEMM_SMEM);
        cudaFuncSetAttribute(hgemm_mma<4>, cudaFuncAttributeMaxDynamicSharedMemorySize, GEMM_SMEM);
        bool ok = cudaStreamCreateWithFlags(&s2, cudaStreamNonBlocking) == cudaSuccess &&
                  cudaStreamCreateWithFlags(&s3, cudaStreamNonBlocking) == cudaSuccess &&
                  cudaEventCreateWithFlags(&evFork, cudaEventDisableTiming) == cudaSuccess &&
                  cudaEventCreateWithFlags(&evJoin, cudaEventDisableTiming) == cudaSuccess &&
                  cudaEventCreateWithFlags(&evEmb, cudaEventDisableTiming) == cudaSuccess &&
                  cudaEventCreateWithFlags(&evSkew, cudaEventDisableTiming) == cudaSuccess &&
                  cudaEventCreateWithFlags(&evW, cudaEventDisableTiming) == cudaSuccess;
        sinit = ok ? 1 : -1;
    }
    bool dual = (sinit == 1);

    // critical-path conversions: layer-0 slices only (+ all xpw, tiny)
    launch_cvt(in_proj_w, pwin, IN_L, 0);
    launch_cvt(dt_proj_w, pwdt, DT_L, 0);
    launch_cvt(out_proj_w, pwout, OUT_L, 0);
    xpw_to_f16_v8<<<(NLAYER * DX * ED / 8 + 255) / 256, 256>>>(x_proj_w, pwxp);
    embed_kernel<<<(Mm * Dd / 4) / 256, 256>>>(tokens, embedding, px);

    if (dual) {
        cudaEventRecord(evFork, 0);
        cudaStreamWaitEvent(s2, evFork, 0);
        cudaStreamWaitEvent(s3, evFork, 0);
        // deferred conversions: layers 1..3 weights, then embedding table
        launch_cvt(in_proj_w + IN_L, pwin + IN_L, (NLAYER - 1) * IN_L, s3);
        launch_cvt(dt_proj_w + DT_L, pwdt + DT_L, (NLAYER - 1) * DT_L, s3);
        launch_cvt(out_proj_w + OUT_L, pwout + OUT_L, (NLAYER - 1) * OUT_L, s3);
        cudaEventRecord(evW, s3);
        launch_cvt(embedding, pemb, (size_t)Vv * Dd, s3);
        cudaEventRecord(evEmb, s3);
    } else {
        launch_cvt(in_proj_w + IN_L, pwin + IN_L, (NLAYER - 1) * IN_L, 0);
        launch_cvt(dt_proj_w + DT_L, pwdt + DT_L, (NLAYER - 1) * DT_L, 0);
        launch_cvt(out_proj_w + OUT_L, pwout + OUT_L, (NLAYER - 1) * OUT_L, 0);
        launch_cvt(embedding, pemb, (size_t)Vv * Dd, 0);
    }

    for (int l = 0; l < NLAYER; l++) {
        if (dual && l == 1) {   // layers >=1 need the deferred weight conversions
            cudaStreamWaitEvent(0, evW, 0);
            cudaStreamWaitEvent(s2, evW, 0);
        }
        for (int b = 0; b < Bb; b++) {
            cudaStream_t sb = (dual && b == 1) ? s2 : (cudaStream_t)0;
            size_t off = (size_t)b * HM;
            // pipeline skew: seq-1's chain starts only after seq-0's layer-0
            // in_proj completes, offsetting the two chains by ~half a layer so
            // their low-occupancy (scan/conv) phases overlap the other stream's
            // GEMM phases instead of coinciding. Pure scheduling; no math change.
            if (dual && l == 0 && b == 1)
                cudaStreamWaitEvent(s2, evSkew, 0);
            rmsnorm_kernel<<<HM, 256, 0, sb>>>(px + off * Dd, norm_w + (size_t)l * Dd,
                                               pxn16 + off * Dd);
            launch_hgemm(4, sb, pxn16 + off * Dd, Dd, pwin + (size_t)l * IN_L, Dd,
                         (float*)(pxz16 + off * 2 * ED), 2 * ED, HM, 2 * ED, 2 * ED, Dd,
                         nullptr, 1, 0);
            if (dual && l == 0 && b == 0)
                cudaEventRecord(evSkew, 0);
            conv_silu_kernel<<<(HM * ED / 2) / 256, 256, 0, sb>>>(
                pxz16 + off * 2 * ED, conv_w + (size_t)l * ED * DCONV,
                conv_b + (size_t)l * ED, pxs16 + off * ED);
            float* partb = pxpp + (size_t)b * XPSPLIT * HM * 128;
            launch_hgemm(0, sb, pxs16 + off * ED, ED, pwxp + (size_t)l * 128 * ED, ED,
                         partb, 128, HM, 128, 128, ED / XPSPLIT, nullptr,
                         XPSPLIT, (size_t)HM * 128);
            xp_reduce<<<(HM * 128 / 4 + 255) / 256, 256, 0, sb>>>(partb, pdbc + off * DX,
                                                                  pdr16 + off * DR);
            launch_hgemm(2, sb, pdr16 + off * DR, DR, pwdt + (size_t)l * DT_L, DR,
                         pdelta + off * ED, ED, HM, ED, ED, DR,
                         dt_proj_b + (size_t)l * ED, 1, 0);
            scan_pass1<<<(ED * CHUNKS) / 64, 256, 0, sb>>>(
                pdelta, pxs16, pdbc, A_log + (size_t)l * ED * Nn, b);
            scan_pass2<<<(ED * Nn) / 256, 256, 0, sb>>>(b);
            scan_pass3<<<(ED * CHUNKS) / 64, 256, 0, sb>>>(
                pdelta, pxs16, pdbc, pxz16, A_log + (size_t)l * ED * Nn,
                D_param + (size_t)l * ED, py16, b);
            launch_hgemm(1, sb, py16 + off * ED, ED, pwout + (size_t)l * OUT_L, ED,
                         px + off * Dd, Dd, HM, Dd, Dd, ED, nullptr, 1, 0);
        }
    }

    // per-sequence final rmsnorm + logits half-GEMM on each sequence's stream.
    if (dual) {
        cudaStreamWaitEvent(0, evEmb, 0);
        cudaStreamWaitEvent(s2, evEmb, 0);
        for (int b = 0; b < Bb; b++) {
            cudaStream_t sb = (b == 1) ? s2 : (cudaStream_t)0;
            size_t off = (size_t)b * HM;
            rmsnorm_kernel<<<HM, 256, 0, sb>>>(px + off * Dd, norm_f_w, pxn16 + off * Dd);
            launch_hgemm(0, sb, pxn16 + off * Dd, Dd, pemb, Dd,
                         logits + off * Vv, Vv, HM, Vv, Vv, Dd, nullptr, 1, 0);
        }
        cudaEventRecord(evJoin, s2);
        cudaStreamWaitEvent(0, evJoin, 0);
    } else {
        rmsnorm_kernel<<<Mm, 256>>>(px, norm_f_w, pxn16);
        launch_hgemm(0, (cudaStream_t)0, pxn16, Dd, pemb, Dd, logits, Vv, Mm, Vv, Vv, Dd,
                     nullptr, 1, 0);
    }
}

// round 16
// speedup vs baseline: 1.0422x; 1.0422x over previous
#include <cuda_runtime.h>
#include <cuda_fp16.h>
#include <cuda_bf16.h>
#include <math.h>
#include <stdint.h>

// ---------------- problem constants ----------------
#define Vv 32000
#define Dd 1024
#define NLAYER 4
#define ED 2048
#define Nn 16
#define DR 64
#define DCONV 4
#define Bb 2
#define Ll 1024
#define Mm (Bb * Ll)      // 2048 tokens
#define HM Ll             // tokens per sequence (1024)
#define DX (DR + 2 * Nn)  // 96
#define CHUNKS 32
#define CLEN (Ll / CHUNKS)   // 32
#define NCH (Bb * ED)        // 4096 channels
#define XPSPLIT 8            // split-K factor for x_proj

// per-layer weight element counts
#define IN_L ((size_t)2 * ED * Dd)
#define DT_L ((size_t)ED * DR)
#define OUT_L ((size_t)Dd * ED)

// ---------------- scratch (no allocs allowed) ----------------
__device__ __align__(256) float g_x[Mm * Dd];
__device__ __align__(256) float g_delta[Mm * ED];
__device__ __align__(256) float g_dbc[Mm * DX];
__device__ __align__(256) float g_xp_part[Bb * XPSPLIT * HM * 128];   // split-K partials
// chunked-scan state: [b][e][chunk][n]
__device__ __align__(256) float g_A[NCH * CHUNKS * Nn];
__device__ __align__(256) float g_hl[NCH * CHUNKS * Nn];
__device__ __align__(256) float g_hs[NCH * CHUNKS * Nn];

// fp16 activation / weight mirrors (zero-initialized; x_proj pad rows stay 0)
__device__ __align__(256) __half h_xz[Mm * 2 * ED];
__device__ __align__(256) __half h_xn[Mm * Dd];
__device__ __align__(256) __half h_xs[Mm * ED];
__device__ __align__(256) __half h_dr[Mm * DR];
__device__ __align__(256) __half h_y[Mm * ED];
__device__ __align__(256) __half h_w_in[NLAYER * 2 * ED * Dd];
__device__ __align__(256) __half h_w_xp[NLAYER * 128 * ED];   // padded 96->128 rows
__device__ __align__(256) __half h_w_dt[NLAYER * ED * DR];
__device__ __align__(256) __half h_w_out[NLAYER * Dd * ED];
__device__ __align__(256) __half h_emb[Vv * Dd];

// ================= small PTX helpers =================
__device__ __forceinline__ uint32_t smem_u32(const void* p) {
    uint32_t a;
    asm("{ .reg .u64 t; cvta.to.shared.u64 t, %1; cvt.u32.u64 %0, t; }" : "=r"(a) : "l"(p));
    return a;
}
__device__ __forceinline__ void ldsm_x4(uint32_t* r, uint32_t addr) {
    asm volatile("ldmatrix.sync.aligned.m8n8.x4.shared.b16 {%0,%1,%2,%3}, [%4];"
                 : "=r"(r[0]), "=r"(r[1]), "=r"(r[2]), "=r"(r[3]) : "r"(addr));
}
__device__ __forceinline__ void mma16816(float* d, const uint32_t* a, uint32_t b0, uint32_t b1) {
    asm volatile("mma.sync.aligned.m16n8k16.row.col.f32.f16.f16.f32 "
                 "{%0,%1,%2,%3}, {%4,%5,%6,%7}, {%8,%9}, {%0,%1,%2,%3};"
                 : "+f"(d[0]), "+f"(d[1]), "+f"(d[2]), "+f"(d[3])
                 : "r"(a[0]), "r"(a[1]), "r"(a[2]), "r"(a[3]), "r"(b0), "r"(b1));
}
#define CP_ASYNC16(dst, src) \
    asm volatile("cp.async.cg.shared.global [%0], [%1], 16;" :: "r"(dst), "l"(src))
#define CP_COMMIT() asm volatile("cp.async.commit_group;" ::: "memory")
#define CP_WAIT1()  asm volatile("cp.async.wait_group 1;" ::: "memory")

// ================= HMMA fp16 GEMM: C(M,N) = A(M,K) @ B(N,K)^T =================
// EPI: 0 store fp32, 1 accumulate fp32 (residual), 2 softplus(acc+bias) fp32,
//      4 store fp16 (C reinterpreted as __half*)
#define BMt 128
#define BNt 128
#define BKt 64
#define STAGES 3
#define ASTRIDE 72
#define TILE_HALFS (128 * ASTRIDE)
#define STAGE_BYTES (2 * TILE_HALFS * 2)
#define GEMM_SMEM (STAGES * STAGE_BYTES)
#define GTHREADS 512

__device__ __forceinline__ void gemm_load_stage(uint32_t sbase, int s,
                                                const __half* A, int lda,
                                                const __half* Bw, int ldb,
                                                int m0, int n0, int c, int tid) {
    uint32_t sa = sbase + s * STAGE_BYTES;
    uint32_t sb = sa + TILE_HALFS * 2;
    const __half* Ap = A + (size_t)m0 * lda + c * BKt;
    const __half* Bp = Bw + (size_t)n0 * ldb + c * BKt;
    int row = tid >> 3, slot = tid & 7;
#pragma unroll
    for (int i = 0; i < 2; i++) {
        int r = row + i * 64;
        CP_ASYNC16(sa + (r * ASTRIDE + slot * 8) * 2, Ap + (size_t)r * lda + slot * 8);
        CP_ASYNC16(sb + (r * ASTRIDE + slot * 8) * 2, Bp + (size_t)r * ldb + slot * 8);
    }
}

template <int EPI>
__global__ void __launch_bounds__(GTHREADS, 1) hgemm_mma(const __half* __restrict__ A, int lda,
                                                         const __half* __restrict__ Bw, int ldb,
                                                         float* __restrict__ C, int ldc,
                                                         int M, int N, int Nstore, int K,
                                                         const float* __restrict__ bias,
                                                         size_t zstrC) {
    extern __shared__ __half sh[];
    uint32_t sbase = smem_u32(sh);
    int tid = threadIdx.x;
    int wid = tid >> 5, lane = tid & 31;
    int warp_m = wid >> 2, warp_n = wid & 3;
    int m0 = blockIdx.y * BMt, n0 = blockIdx.x * BNt;
    int kz = blockIdx.z;
    A += (size_t)kz * K;
    Bw += (size_t)kz * K;
    C += (size_t)kz * zstrC;
    int KC = K / BKt;

    float acc[2][4][4];
#pragma unroll
    for (int i = 0; i < 2; i++)
#pragma unroll
        for (int j = 0; j < 4; j++)
#pragma unroll
            for (int k = 0; k < 4; k++) acc[i][j][k] = 0.f;

#pragma unroll
    for (int s = 0; s < STAGES - 1; s++) {
        if (s < KC) gemm_load_stage(sbase, s, A, lda, Bw, ldb, m0, n0, s, tid);
        CP_COMMIT();
    }

    int lrow = lane & 15;
    int kcol8 = (lane >> 4) * 8;
    uint32_t afr[2][2][4], bfr[2][2][4];

    for (int c = 0; c < KC; c++) {
        CP_WAIT1();
        __syncthreads();

        int cn = c + STAGES - 1;
        if (cn < KC)
            gemm_load_stage(sbase, cn % STAGES, A, lda, Bw, ldb, m0, n0, cn, tid);
        CP_COMMIT();

        uint32_t sa = sbase + (c % STAGES) * STAGE_BYTES;
        uint32_t sb = sa + TILE_HALFS * 2;

#pragma unroll
        for (int mf = 0; mf < 2; mf++)
            ldsm_x4(afr[0][mf], sa + ((warp_m * 32 + mf * 16 + lrow) * ASTRIDE + kcol8) * 2);
#pragma unroll
        for (int nh = 0; nh < 2; nh++)
            ldsm_x4(bfr[0][nh], sb + ((warp_n * 32 + nh * 16 + lrow) * ASTRIDE + kcol8) * 2);

#pragma unroll
        for (int kk = 0; kk < 4; kk++) {
            int b = kk & 1;
            if (kk < 3) {
                int kof = (kk + 1) * 16 + kcol8;
#pragma unroll
                for (int mf = 0; mf < 2; mf++)
                    ldsm_x4(afr[b ^ 1][mf], sa + ((warp_m * 32 + mf * 16 + lrow) * ASTRIDE + kof) * 2);
#pragma unroll
                for (int nh = 0; nh < 2; nh++)
                    ldsm_x4(bfr[b ^ 1][nh], sb + ((warp_n * 32 + nh * 16 + lrow) * ASTRIDE + kof) * 2);
            }
#pragma unroll
            for (int mf = 0; mf < 2; mf++)
#pragma unroll
                for (int nf = 0; nf < 4; nf++) {
                    int nh = nf >> 1, odd = nf & 1;
                    mma16816(acc[mf][nf], afr[b][mf], bfr[b][nh][odd], bfr[b][nh][odd + 2]);
                }
        }
    }

    int g = lane >> 2, t4 = lane & 3;
#pragma unroll
    for (int mf = 0; mf < 2; mf++) {
        int row0 = m0 + warp_m * 32 + mf * 16 + g;
#pragma unroll
        for (int nf = 0; nf < 4; nf++) {
            int n = n0 + warp_n * 32 + nf * 8 + 2 * t4;
            if (n >= Nstore) continue;
            float2 v0 = make_float2(acc[mf][nf][0], acc[mf][nf][1]);
            float2 v1 = make_float2(acc[mf][nf][2], acc[mf][nf][3]);
            if (EPI == 4) {
                __half* Ch = (__half*)C;
                *(__half2*)(Ch + (size_t)row0 * ldc + n) = __floats2half2_rn(v0.x, v0.y);
                *(__half2*)(Ch + (size_t)(row0 + 8) * ldc + n) = __floats2half2_rn(v1.x, v1.y);
                continue;
            }
            float* C0 = C + (size_t)row0 * ldc;
            float* C1 = C0 + (size_t)8 * ldc;
            if (EPI == 1) {
                float2 o0 = *(float2*)(C0 + n);
                float2 o1 = *(float2*)(C1 + n);
                v0.x += o0.x; v0.y += o0.y;
                v1.x += o1.x; v1.y += o1.y;
            }
            if (EPI == 2) {
                float b0 = bias[n], b1 = bias[n + 1];
                v0.x += b0; v0.y += b1; v1.x += b0; v1.y += b1;
                v0.x = (v0.x > 20.f) ? v0.x : __logf(1.f + __expf(v0.x));
                v0.y = (v0.y > 20.f) ? v0.y : __logf(1.f + __expf(v0.y));
                v1.x = (v1.x > 20.f) ? v1.x : __logf(1.f + __expf(v1.x));
                v1.y = (v1.y > 20.f) ? v1.y : __logf(1.f + __expf(v1.y));
            }
            *(float2*)(C0 + n) = v0;
            *(float2*)(C1 + n) = v1;
        }
    }
}

// split-K reduce (per sequence, float4-vectorized): dbc (fp32) + delta_r (fp16)
__global__ void __launch_bounds__(256) xp_reduce(const float* __restrict__ part,
                                                 float* __restrict__ dbc,
                                                 __half* __restrict__ dr16) {
    int i = blockIdx.x * 256 + threadIdx.x;   // over HM*128/4 vec4 units
    if (i >= HM * 128 / 4) return;
    int m = i >> 5;            // 32 vec4 per row
    int col = (i & 31) * 4;
    float4 s = ((const float4*)part)[i];
#pragma unroll
    for (int z = 1; z < XPSPLIT; z++) {
        float4 v = ((const float4*)(part + (size_t)z * (HM * 128)))[i];
        s.x += v.x; s.y += v.y; s.z += v.z; s.w += v.w;
    }
    if (col < DX) *(float4*)(dbc + m * DX + col) = s;
    if (col < DR) {
        __half2 a = __floats2half2_rn(s.x, s.y);
        __half2 b = __floats2half2_rn(s.z, s.w);
        uint32_t pa = *(uint32_t*)&a, pb = *(uint32_t*)&b;
        uint2 o = make_uint2(pa, pb);
        *(uint2*)(dr16 + m * DR + col) = o;
    }
}

// ================= conversion kernels =================
__device__ __forceinline__ void cvt8(const float4* sp, uint4* dp) {
    float4 a = sp[0], b = sp[1];
    __half2 h0 = __floats2half2_rn(a.x, a.y);
    __half2 h1 = __floats2half2_rn(a.z, a.w);
    __half2 h2 = __floats2half2_rn(b.x, b.y);
    __half2 h3 = __floats2half2_rn(b.z, b.w);
    uint4 o;
    o.x = *(uint32_t*)&h0; o.y = *(uint32_t*)&h1;
    o.z = *(uint32_t*)&h2; o.w = *(uint32_t*)&h3;
    *dp = o;
}

__global__ void __launch_bounds__(256) f16cvt(const float* __restrict__ s,
                                              __half* __restrict__ d, int n8) {
    int i = blockIdx.x * 256 + threadIdx.x;
    if (i >= n8) return;
    cvt8((const float4*)s + 2 * i, (uint4*)d + i);
}

// merged layer-0 weight conversion (in_proj | dt_proj | out_proj slices)
#define C0A ((int)(IN_L / 8))
#define C0B ((int)(DT_L / 8))
#define C0C ((int)(OUT_L / 8))
__global__ void __launch_bounds__(256) convert_wts0(const float* __restrict__ s1, __half* __restrict__ d1,
                                                    const float* __restrict__ s2, __half* __restrict__ d2,
                                                    const float* __restrict__ s3, __half* __restrict__ d3) {
    int i = blockIdx.x * 256 + threadIdx.x;
    if (i >= C0A + C0B + C0C) return;
    const float* s; __half* d; int j;
    if (i < C0A)            { s = s1; d = d1; j = i; }
    else if (i < C0A + C0B) { s = s2; d = d2; j = i - C0A; }
    else                    { s = s3; d = d3; j = i - C0A - C0B; }
    cvt8((const float4*)s + 2 * j, (uint4*)d + j);
}

__global__ void __launch_bounds__(256) xpw_to_f16_v8(const float* __restrict__ s,
                                                     __half* __restrict__ d) {
    int i = blockIdx.x * 256 + threadIdx.x;
    if (i >= NLAYER * DX * ED / 8) return;
    int l = i / (DX * ED / 8);
    int rem = i % (DX * ED / 8);
    int r = rem / (ED / 8);
    int cv = rem % (ED / 8);
    cvt8((const float4*)(s + ((size_t)(l * DX + r) * ED)) + 2 * cv,
         (uint4*)(d + ((size_t)l * 128 + r) * ED) + cv);
}

__global__ void __launch_bounds__(256) embed_kernel(const int* __restrict__ tok,
                                                    const float* __restrict__ emb,
                                                    float* __restrict__ out) {
    int idx = blockIdx.x * 256 + threadIdx.x;
    int m = idx >> 8;
    int d4 = idx & 255;
    ((float4*)out)[idx] = ((const float4*)(emb + (size_t)tok[m] * Dd))[d4];
}

__global__ void __launch_bounds__(256) rmsnorm_kernel(const float* __restrict__ x,
                                                      const float* __restrict__ w,
                                                      __half* __restrict__ out) {
    int row = blockIdx.x;
    const float* xr = x + (size_t)row * Dd;
    float v[4];
    float s = 0.f;
#pragma unroll
    for (int i = 0; i < 4; i++) {
        v[i] = xr[threadIdx.x + i * 256];
        s += v[i] * v[i];
    }
#pragma unroll
    for (int o = 16; o; o >>= 1) s += __shfl_xor_sync(0xffffffffu, s, o);
    __shared__ float ss[8];
    if ((threadIdx.x & 31) == 0) ss[threadIdx.x >> 5] = s;
    __syncthreads();
    if (threadIdx.x < 32) {
        float t = (threadIdx.x < 8) ? ss[threadIdx.x] : 0.f;
#pragma unroll
        for (int o = 4; o; o >>= 1) t += __shfl_xor_sync(0xffffffffu, t, o);
        if (threadIdx.x == 0) ss[0] = t;
    }
    __syncthreads();
    float r = rsqrtf(ss[0] * (1.f / (float)Dd) + 1e-5f);
    __half* orow = out + (size_t)row * Dd;
#pragma unroll
    for (int i = 0; i < 4; i++) {
        int d = threadIdx.x + i * 256;
        orow[d] = __float2half(v[i] * r * w[d]);
    }
}

// depthwise causal conv + bias + silu (per sequence)
__global__ void __launch_bounds__(256) conv_silu_kernel(const __half* __restrict__ xz,
                                                        const float* __restrict__ cw,
                                                        const float* __restrict__ cb,
                                                        __half* __restrict__ xs16) {
    int idx = blockIdx.x * 256 + threadIdx.x;   // over HM*ED/2
    int e2 = idx & (ED / 2 - 1);
    int e = e2 * 2;
    int m = idx >> 10;
    int l = m & (Ll - 1);
    const __half* xin = xz + (size_t)m * (2 * ED) + e;
    float4 wa = *(const float4*)(cw + e * 4);
    float4 wb = *(const float4*)(cw + e * 4 + 4);
    float2 cbv = *(const float2*)(cb + e);
    float2 x0 = __half22float2(*(const __half2*)xin);
    float a0 = cbv.x + wa.w * x0.x;
    float a1 = cbv.y + wb.w * x0.y;
    if (l >= 1) {
        float2 x1 = __half22float2(*(const __half2*)(xin - 2 * ED));
        a0 += wa.z * x1.x; a1 += wb.z * x1.y;
    }
    if (l >= 2) {
        float2 x2 = __half22float2(*(const __half2*)(xin - 4 * ED));
        a0 += wa.y * x2.x; a1 += wb.y * x2.y;
    }
    if (l >= 3) {
        float2 x3 = __half22float2(*(const __half2*)(xin - 6 * ED));
        a0 += wa.x * x3.x; a1 += wb.x * x3.y;
    }
    float r0 = a0 / (1.f + __expf(-a0));
    float r1 = a1 / (1.f + __expf(-a1));
    *(__half2*)(xs16 + (size_t)m * ED + e) = __floats2half2_rn(r0, r1);
}

// ================= chunked selective scan (4 lanes x 4 states, 32 chunks) ========
__global__ void __launch_bounds__(256) scan_pass1(const float* __restrict__ delta,
                                                  const __half* __restrict__ xs,
                                                  const float* __restrict__ dbc,
                                                  const float* __restrict__ A_log,
                                                  int bsel) {
    int u = blockIdx.x * 64 + (threadIdx.x >> 2);   // 0 .. ED*CHUNKS-1
    int j = threadIdx.x & 3;                        // states 4j..4j+3
    int c = u >> 11;
    int e = u & (ED - 1);
    float4 al = *(const float4*)(A_log + e * Nn + 4 * j);
    float a0 = -__expf(al.x) * 1.44269504f;
    float a1 = -__expf(al.y) * 1.44269504f;
    float a2 = -__expf(al.z) * 1.44269504f;
    float a3 = -__expf(al.w) * 1.44269504f;
    size_t t0 = (size_t)bsel * Ll + c * CLEN;
    const float* pd = delta + t0 * ED + e;
    const __half* pxs = xs + t0 * ED + e;
    const float* pB = dbc + t0 * DX + DR + 4 * j;
    float h0 = 0.f, h1 = 0.f, h2 = 0.f, h3 = 0.f;
    float s0 = 0.f, s1 = 0.f, s2 = 0.f, s3 = 0.f;
#pragma unroll 8
    for (int t = 0; t < CLEN; t++) {
        float d = *pd;
        float xv = __half2float(*pxs);
        float4 Bv = *(const float4*)pB;
        float e0 = d * a0, e1 = d * a1, e2v = d * a2, e3 = d * a3;
        s0 += e0; s1 += e1; s2 += e2v; s3 += e3;
        float dx = d * xv;
        h0 = fmaf(exp2f(e0), h0, dx * Bv.x);
        h1 = fmaf(exp2f(e1), h1, dx * Bv.y);
        h2 = fmaf(exp2f(e2v), h2, dx * Bv.z);
        h3 = fmaf(exp2f(e3), h3, dx * Bv.w);
        pd += ED; pxs += ED; pB += DX;
    }
    int o = (((bsel * ED + e) * CHUNKS) + c) * Nn + 4 * j;
    *(float4*)(g_hl + o) = make_float4(h0, h1, h2, h3);
    *(float4*)(g_A + o) = make_float4(exp2f(s0), exp2f(s1), exp2f(s2), exp2f(s3));
}

// pass2: serial prefix over chunks -> start state per chunk (per sequence)
__global__ void __launch_bounds__(256) scan_pass2(int bsel) {
    int i = blockIdx.x * 256 + threadIdx.x;   // 0 .. ED*Nn-1
    int e = i >> 4, n = i & 15;
    int chb = (bsel * ED + e) * CHUNKS;
    float hs = 0.f;
#pragma unroll
    for (int c = 0; c < CHUNKS; c++) {
        int o = (chb + c) * Nn + n;
        g_hs[o] = hs;
        hs = fmaf(g_A[o], hs, g_hl[o]);
    }
}

__global__ void __launch_bounds__(256) scan_pass3(const float* __restrict__ delta,
                                                  const __half* __restrict__ xs,
                                                  const float* __restrict__ dbc,
                                                  const __half* __restrict__ xz,
                                                  const float* __restrict__ A_log,
                                                  const float* __restrict__ Dp,
                                                  __half* __restrict__ y,
                                                  int bsel) {
    int u = blockIdx.x * 64 + (threadIdx.x >> 2);
    int j = threadIdx.x & 3;
    int c = u >> 11;
    int e = u & (ED - 1);
    float4 al = *(const float4*)(A_log + e * Nn + 4 * j);
    float a0 = -__expf(al.x) * 1.44269504f;
    float a1 = -__expf(al.y) * 1.44269504f;
    float a2 = -__expf(al.z) * 1.44269504f;
    float a3 = -__expf(al.w) * 1.44269504f;
    float dpar = Dp[e];

    int o = (((bsel * ED + e) * CHUNKS) + c) * Nn + 4 * j;
    float4 Hs = *(const float4*)(g_hs + o);
    float h0 = Hs.x, h1 = Hs.y, h2 = Hs.z, h3 = Hs.w;

    size_t t0 = (size_t)bsel * Ll + c * CLEN;
    const float* pd = delta + t0 * ED + e;
    const __half* pxs = xs + t0 * ED + e;
    const float* pB = dbc + t0 * DX + DR + 4 * j;
    const float* pC = dbc + t0 * DX + DR + Nn + 4 * j;
    const __half* pz = xz + t0 * (2 * ED) + ED + e;
    __half* py = y + t0 * ED + e;

#pragma unroll 8
    for (int t = 0; t < CLEN; t++) {
        float d = *pd;
        float xv = __half2float(*pxs);
        float4 Bv = *(const float4*)pB;
        float4 Cv = *(const float4*)pC;
        float dx = d * xv;
        h0 = fmaf(exp2f(d * a0), h0, dx * Bv.x);
        h1 = fmaf(exp2f(d * a1), h1, dx * Bv.y);
        h2 = fmaf(exp2f(d * a2), h2, dx * Bv.z);
        h3 = fmaf(exp2f(d * a3), h3, dx * Bv.w);
        float p = h0 * Cv.x + h1 * Cv.y + h2 * Cv.z + h3 * Cv.w;
        p += __shfl_xor_sync(0xffffffffu, p, 1);
        p += __shfl_xor_sync(0xffffffffu, p, 2);
        if (j == 0) {
            float z = __half2float(*pz);
            float sz = z / (1.f + __expf(-z));
            py[0] = __float2half((p + dpar * xv) * sz);
        }
        pd += ED; pxs += ED; pB += DX; pC += DX; pz += 2 * ED; py += ED;
    }
}

// ---------------- host side ----------------
static void launch_hgemm(int epi, cudaStream_t st,
                         const __half* A, int lda, const __half* B, int ldb,
                         float* C, int ldc, int M, int N, int Nstore, int K,
                         const float* bias, int zsplit, size_t zstrC) {
    dim3 grid(N / BNt, M / BMt, zsplit);
    if (epi == 0)
        hgemm_mma<0><<<grid, GTHREADS, GEMM_SMEM, st>>>(A, lda, B, ldb, C, ldc, M, N, Nstore, K, bias, zstrC);
    else if (epi == 1)
        hgemm_mma<1><<<grid, GTHREADS, GEMM_SMEM, st>>>(A, lda, B, ldb, C, ldc, M, N, Nstore, K, bias, zstrC);
    else if (epi == 2)
        hgemm_mma<2><<<grid, GTHREADS, GEMM_SMEM, st>>>(A, lda, B, ldb, C, ldc, M, N, Nstore, K, bias, zstrC);
    else
        hgemm_mma<4><<<grid, GTHREADS, GEMM_SMEM, st>>>(A, lda, B, ldb, C, ldc, M, N, Nstore, K, bias, zstrC);
}

static void launch_cvt(const float* s, __half* d, size_t elems, cudaStream_t st) {
    int n8 = (int)(elems / 8);
    f16cvt<<<(n8 + 255) / 256, 256, 0, st>>>(s, d, n8);
}

extern "C" void kernel_launch(void* const* d_in, const int* in_sizes, int n_in,
                              void* d_out, int out_size) {
    const int* tokens = (const int*)d_in[0];
    const float* embedding = (const float*)d_in[1];
    const float* in_proj_w = (const float*)d_in[2];
    const float* conv_w = (const float*)d_in[3];
    const float* conv_b = (const float*)d_in[4];
    const float* x_proj_w = (const float*)d_in[5];
    const float* dt_proj_w = (const float*)d_in[6];
    const float* dt_proj_b = (const float*)d_in[7];
    const float* A_log = (const float*)d_in[8];
    const float* D_param = (const float*)d_in[9];
    const float* out_proj_w = (const float*)d_in[10];
    const float* norm_w = (const float*)d_in[11];
    const float* norm_f_w = (const float*)d_in[12];
    float* logits = (float*)d_out;

    float *px, *pdelta, *pdbc, *pxpp;
    __half *pxz16, *pxn16, *pxs16, *pdr16, *py16, *pwin, *pwxp, *pwdt, *pwout, *pemb;
    cudaGetSymbolAddress((void**)&px, g_x);
    cudaGetSymbolAddress((void**)&pdelta, g_delta);
    cudaGetSymbolAddress((void**)&pdbc, g_dbc);
    cudaGetSymbolAddress((void**)&pxpp, g_xp_part);
    cudaGetSymbolAddress((void**)&pxz16, h_xz);
    cudaGetSymbolAddress((void**)&pxn16, h_xn);
    cudaGetSymbolAddress((void**)&pxs16, h_xs);
    cudaGetSymbolAddress((void**)&pdr16, h_dr);
    cudaGetSymbolAddress((void**)&py16, h_y);
    cudaGetSymbolAddress((void**)&pwin, h_w_in);
    cudaGetSymbolAddress((void**)&pwxp, h_w_xp);
    cudaGetSymbolAddress((void**)&pwdt, h_w_dt);
    cudaGetSymbolAddress((void**)&pwout, h_w_out);
    cudaGetSymbolAddress((void**)&pemb, h_emb);

    // one-time smem attribute setup + side streams/events
    static cudaStream_t s2 = nullptr, s3 = nullptr;
    static cudaEvent_t evFork = nullptr, evJoin = nullptr, evEmb = nullptr, evW = nullptr;
    static int sinit = 0;
    if (!sinit) {
        cudaFuncSetAttribute(hgemm_mma<0>, cudaFuncAttributeMaxDynamicSharedMemorySize, GEMM_SMEM);
        cudaFuncSetAttribute(hgemm_mma<1>, cudaFuncAttributeMaxDynamicSharedMemorySize, GEMM_SMEM);
        cudaFuncSetAttribute(hgemm_mma<2>, cudaFuncAttributeMaxDynamicSharedMemorySize, GEMM_SMEM);
        cudaFuncSetAttribute(hgemm_mma<4>, cudaFuncAttributeMaxDynamicSharedMemorySize, GEMM_SMEM);
        bool ok = cudaStreamCreateWithFlags(&s2, cudaStreamNonBlocking) == cudaSuccess &&
                  cudaStreamCreateWithFlags(&s3, cudaStreamNonBlocking) == cudaSuccess &&
                  cudaEventCreateWithFlags(&evFork, cudaEventDisableTiming) == cudaSuccess &&
                  cudaEventCreateWithFlags(&evJoin, cudaEventDisableTiming) == cudaSuccess &&
                  cudaEventCreateWithFlags(&evEmb, cudaEventDisableTiming) == cudaSuccess &&
                  cudaEventCreateWithFlags(&evW, cudaEventDisableTiming) == cudaSuccess;
        sinit = ok ? 1 : -1;
    }
    bool dual = (sinit == 1);

    // critical-path conversions: layer-0 slices in ONE kernel (+ all xpw, tiny)
    convert_wts0<<<(C0A + C0B + C0C + 255) / 256, 256>>>(in_proj_w, pwin,
                                                         dt_proj_w, pwdt,
                                                         out_proj_w, pwout);
    xpw_to_f16_v8<<<(NLAYER * DX * ED / 8 + 255) / 256, 256>>>(x_proj_w, pwxp);
    embed_kernel<<<(Mm * Dd / 4) / 256, 256>>>(tokens, embedding, px);

    if (dual) {
        cudaEventRecord(evFork, 0);
        cudaStreamWaitEvent(s2, evFork, 0);
        cudaStreamWaitEvent(s3, evFork, 0);
        // deferred conversions: layers 1..3 weights, then embedding table
        launch_cvt(in_proj_w + IN_L, pwin + IN_L, (NLAYER - 1) * IN_L, s3);
        launch_cvt(dt_proj_w + DT_L, pwdt + DT_L, (NLAYER - 1) * DT_L, s3);
        launch_cvt(out_proj_w + OUT_L, pwout + OUT_L, (NLAYER - 1) * OUT_L, s3);
        cudaEventRecord(evW, s3);
        launch_cvt(embedding, pemb, (size_t)Vv * Dd, s3);
        cudaEventRecord(evEmb, s3);
    } else {
        launch_cvt(in_proj_w + IN_L, pwin + IN_L, (NLAYER - 1) * IN_L, 0);
        launch_cvt(dt_proj_w + DT_L, pwdt + DT_L, (NLAYER - 1) * DT_L, 0);
        launch_cvt(out_proj_w + OUT_L, pwout + OUT_L, (NLAYER - 1) * OUT_L, 0);
        launch_cvt(embedding, pemb, (size_t)Vv * Dd, 0);
    }

    for (int l = 0; l < NLAYER; l++) {
        if (dual && l == 1) {   // layers >=1 need the deferred weight conversions
            cudaStreamWaitEvent(0, evW, 0);
            cudaStreamWaitEvent(s2, evW, 0);
        }
        for (int b = 0; b < Bb; b++) {
            cudaStream_t sb = (dual && b == 1) ? s2 : (cudaStream_t)0;
            size_t off = (size_t)b * HM;
            rmsnorm_kernel<<<HM, 256, 0, sb>>>(px + off * Dd, norm_w + (size_t)l * Dd,
                                               pxn16 + off * Dd);
            launch_hgemm(4, sb, pxn16 + off * Dd, Dd, pwin + (size_t)l * IN_L, Dd,
                         (float*)(pxz16 + off * 2 * ED), 2 * ED, HM, 2 * ED, 2 * ED, Dd,
                         nullptr, 1, 0);
            conv_silu_kernel<<<(HM * ED / 2) / 256, 256, 0, sb>>>(
                pxz16 + off * 2 * ED, conv_w + (size_t)l * ED * DCONV,
                conv_b + (size_t)l * ED, pxs16 + off * ED);
            float* partb = pxpp + (size_t)b * XPSPLIT * HM * 128;
            launch_hgemm(0, sb, pxs16 + off * ED, ED, pwxp + (size_t)l * 128 * ED, ED,
                         partb, 128, HM, 128, 128, ED / XPSPLIT, nullptr,
                         XPSPLIT, (size_t)HM * 128);
            xp_reduce<<<(HM * 128 / 4 + 255) / 256, 256, 0, sb>>>(partb, pdbc + off * DX,
                                                                  pdr16 + off * DR);
            launch_hgemm(2, sb, pdr16 + off * DR, DR, pwdt + (size_t)l * DT_L, DR,
                         pdelta + off * ED, ED, HM, ED, ED, DR,
                         dt_proj_b + (size_t)l * ED, 1, 0);
            scan_pass1<<<(ED * CHUNKS) / 64, 256, 0, sb>>>(
                pdelta, pxs16, pdbc, A_log + (size_t)l * ED * Nn, b);
            scan_pass2<<<(ED * Nn) / 256, 256, 0, sb>>>(b);
            scan_pass3<<<(ED * CHUNKS) / 64, 256, 0, sb>>>(
                pdelta, pxs16, pdbc, pxz16, A_log + (size_t)l * ED * Nn,
                D_param + (size_t)l * ED, py16, b);
            launch_hgemm(1, sb, py16 + off * ED, ED, pwout + (size_t)l * OUT_L, ED,
                         px + off * Dd, Dd, HM, Dd, Dd, ED, nullptr, 1, 0);
        }
    }

    // per-sequence final rmsnorm + logits half-GEMM on each sequence's stream.
    if (dual) {
        cudaStreamWaitEvent(0, evEmb, 0);
        cudaStreamWaitEvent(s2, evEmb, 0);
        for (int b = 0; b < Bb; b++) {
            cudaStream_t sb = (b == 1) ? s2 : (cudaStream_t)0;
            size_t off = (size_t)b * HM;
            rmsnorm_kernel<<<HM, 256, 0, sb>>>(px + off * Dd, norm_f_w, pxn16 + off * Dd);
            launch_hgemm(0, sb, pxn16 + off * Dd, Dd, pemb, Dd,
                         logits + off * Vv, Vv, HM, Vv, Vv, Dd, nullptr, 1, 0);
        }
        cudaEventRecord(evJoin, s2);
        cudaStreamWaitEvent(0, evJoin, 0);
    } else {
        rmsnorm_kernel<<<Mm, 256>>>(px, norm_f_w, pxn16);
        launch_hgemm(0, (cudaStream_t)0, pxn16, Dd, pemb, Dd, logits, Vv, Mm, Vv, Vv, Dd,
                     nullptr, 1, 0);
    }
}

// round 17
// speedup vs baseline: 1.0532x; 1.0106x over previous
#include <cuda_runtime.h>
#include <cuda_fp16.h>
#include <cuda_bf16.h>
#include <math.h>
#include <stdint.h>

// ---------------- problem constants ----------------
#define Vv 32000
#define Dd 1024
#define NLAYER 4
#define ED 2048
#define Nn 16
#define DR 64
#define DCONV 4
#define Bb 2
#define Ll 1024
#define Mm (Bb * Ll)      // 2048 tokens
#define HM Ll             // tokens per sequence (1024)
#define DX (DR + 2 * Nn)  // 96
#define CHUNKS 32
#define CLEN (Ll / CHUNKS)   // 32
#define NCH (Bb * ED)        // 4096 channels
#define XPSPLIT 8            // split-K factor for x_proj

// per-layer weight element counts
#define IN_L ((size_t)2 * ED * Dd)
#define DT_L ((size_t)ED * DR)
#define OUT_L ((size_t)Dd * ED)

// ---------------- scratch (no allocs allowed) ----------------
__device__ __align__(256) float g_x[Mm * Dd];
__device__ __align__(256) float g_delta[Mm * ED];
__device__ __align__(256) float g_dbc[Mm * DX];
__device__ __align__(256) float g_xp_part[Bb * XPSPLIT * HM * 128];   // split-K partials
// chunked-scan state: [b][e][chunk][n]
__device__ __align__(256) float g_A[NCH * CHUNKS * Nn];
__device__ __align__(256) float g_hl[NCH * CHUNKS * Nn];
__device__ __align__(256) float g_hs[NCH * CHUNKS * Nn];

// fp16 activation / weight mirrors (zero-initialized; x_proj pad rows stay 0)
__device__ __align__(256) __half h_xz[Mm * 2 * ED];
__device__ __align__(256) __half h_xn[Mm * Dd];
__device__ __align__(256) __half h_xs[Mm * ED];
__device__ __align__(256) __half h_dr[Mm * DR];
__device__ __align__(256) __half h_y[Mm * ED];
__device__ __align__(256) __half h_w_in[NLAYER * 2 * ED * Dd];
__device__ __align__(256) __half h_w_xp[NLAYER * 128 * ED];   // padded 96->128 rows
__device__ __align__(256) __half h_w_dt[NLAYER * ED * DR];
__device__ __align__(256) __half h_w_out[NLAYER * Dd * ED];
__device__ __align__(256) __half h_emb[Vv * Dd];

// ================= small PTX helpers =================
__device__ __forceinline__ uint32_t smem_u32(const void* p) {
    uint32_t a;
    asm("{ .reg .u64 t; cvta.to.shared.u64 t, %1; cvt.u32.u64 %0, t; }" : "=r"(a) : "l"(p));
    return a;
}
__device__ __forceinline__ void ldsm_x4(uint32_t* r, uint32_t addr) {
    asm volatile("ldmatrix.sync.aligned.m8n8.x4.shared.b16 {%0,%1,%2,%3}, [%4];"
                 : "=r"(r[0]), "=r"(r[1]), "=r"(r[2]), "=r"(r[3]) : "r"(addr));
}
__device__ __forceinline__ void mma16816(float* d, const uint32_t* a, uint32_t b0, uint32_t b1) {
    asm volatile("mma.sync.aligned.m16n8k16.row.col.f32.f16.f16.f32 "
                 "{%0,%1,%2,%3}, {%4,%5,%6,%7}, {%8,%9}, {%0,%1,%2,%3};"
                 : "+f"(d[0]), "+f"(d[1]), "+f"(d[2]), "+f"(d[3])
                 : "r"(a[0]), "r"(a[1]), "r"(a[2]), "r"(a[3]), "r"(b0), "r"(b1));
}
#define CP_ASYNC16(dst, src) \
    asm volatile("cp.async.cg.shared.global [%0], [%1], 16;" :: "r"(dst), "l"(src))
#define CP_COMMIT() asm volatile("cp.async.commit_group;" ::: "memory")
#define CP_WAIT1()  asm volatile("cp.async.wait_group 1;" ::: "memory")

// ================= HMMA fp16 GEMM: C(M,N) = A(M,K) @ B(N,K)^T =================
// EPI: 0 store fp32, 1 accumulate fp32 (residual), 2 softplus(acc+bias) fp32,
//      4 store fp16 (C reinterpreted as __half*)
#define BMt 128
#define BNt 128
#define BKt 64
#define STAGES 3
#define ASTRIDE 72
#define TILE_HALFS (128 * ASTRIDE)
#define STAGE_BYTES (2 * TILE_HALFS * 2)
#define GEMM_SMEM (STAGES * STAGE_BYTES)
#define GTHREADS 512

__device__ __forceinline__ void gemm_load_stage(uint32_t sbase, int s,
                                                const __half* A, int lda,
                                                const __half* Bw, int ldb,
                                                int m0, int n0, int c, int tid) {
    uint32_t sa = sbase + s * STAGE_BYTES;
    uint32_t sb = sa + TILE_HALFS * 2;
    const __half* Ap = A + (size_t)m0 * lda + c * BKt;
    const __half* Bp = Bw + (size_t)n0 * ldb + c * BKt;
    int row = tid >> 3, slot = tid & 7;
#pragma unroll
    for (int i = 0; i < 2; i++) {
        int r = row + i * 64;
        CP_ASYNC16(sa + (r * ASTRIDE + slot * 8) * 2, Ap + (size_t)r * lda + slot * 8);
        CP_ASYNC16(sb + (r * ASTRIDE + slot * 8) * 2, Bp + (size_t)r * ldb + slot * 8);
    }
}

template <int EPI>
__global__ void __launch_bounds__(GTHREADS, 1) hgemm_mma(const __half* __restrict__ A, int lda,
                                                         const __half* __restrict__ Bw, int ldb,
                                                         float* __restrict__ C, int ldc,
                                                         int M, int N, int Nstore, int K,
                                                         const float* __restrict__ bias,
                                                         size_t zstrC) {
    extern __shared__ __half sh[];
    uint32_t sbase = smem_u32(sh);
    int tid = threadIdx.x;
    int wid = tid >> 5, lane = tid & 31;
    int warp_m = wid >> 2, warp_n = wid & 3;
    int m0 = blockIdx.y * BMt, n0 = blockIdx.x * BNt;
    int kz = blockIdx.z;
    A += (size_t)kz * K;
    Bw += (size_t)kz * K;
    C += (size_t)kz * zstrC;
    int KC = K / BKt;

    float acc[2][4][4];
#pragma unroll
    for (int i = 0; i < 2; i++)
#pragma unroll
        for (int j = 0; j < 4; j++)
#pragma unroll
            for (int k = 0; k < 4; k++) acc[i][j][k] = 0.f;

#pragma unroll
    for (int s = 0; s < STAGES - 1; s++) {
        if (s < KC) gemm_load_stage(sbase, s, A, lda, Bw, ldb, m0, n0, s, tid);
        CP_COMMIT();
    }

    int lrow = lane & 15;
    int kcol8 = (lane >> 4) * 8;
    uint32_t afr[2][2][4], bfr[2][2][4];

    for (int c = 0; c < KC; c++) {
        CP_WAIT1();
        __syncthreads();

        int cn = c + STAGES - 1;
        if (cn < KC)
            gemm_load_stage(sbase, cn % STAGES, A, lda, Bw, ldb, m0, n0, cn, tid);
        CP_COMMIT();

        uint32_t sa = sbase + (c % STAGES) * STAGE_BYTES;
        uint32_t sb = sa + TILE_HALFS * 2;

#pragma unroll
        for (int mf = 0; mf < 2; mf++)
            ldsm_x4(afr[0][mf], sa + ((warp_m * 32 + mf * 16 + lrow) * ASTRIDE + kcol8) * 2);
#pragma unroll
        for (int nh = 0; nh < 2; nh++)
            ldsm_x4(bfr[0][nh], sb + ((warp_n * 32 + nh * 16 + lrow) * ASTRIDE + kcol8) * 2);

#pragma unroll
        for (int kk = 0; kk < 4; kk++) {
            int b = kk & 1;
            if (kk < 3) {
                int kof = (kk + 1) * 16 + kcol8;
#pragma unroll
                for (int mf = 0; mf < 2; mf++)
                    ldsm_x4(afr[b ^ 1][mf], sa + ((warp_m * 32 + mf * 16 + lrow) * ASTRIDE + kof) * 2);
#pragma unroll
                for (int nh = 0; nh < 2; nh++)
                    ldsm_x4(bfr[b ^ 1][nh], sb + ((warp_n * 32 + nh * 16 + lrow) * ASTRIDE + kof) * 2);
            }
#pragma unroll
            for (int mf = 0; mf < 2; mf++)
#pragma unroll
                for (int nf = 0; nf < 4; nf++) {
                    int nh = nf >> 1, odd = nf & 1;
                    mma16816(acc[mf][nf], afr[b][mf], bfr[b][nh][odd], bfr[b][nh][odd + 2]);
                }
        }
    }

    int g = lane >> 2, t4 = lane & 3;
#pragma unroll
    for (int mf = 0; mf < 2; mf++) {
        int row0 = m0 + warp_m * 32 + mf * 16 + g;
#pragma unroll
        for (int nf = 0; nf < 4; nf++) {
            int n = n0 + warp_n * 32 + nf * 8 + 2 * t4;
            if (n >= Nstore) continue;
            float2 v0 = make_float2(acc[mf][nf][0], acc[mf][nf][1]);
            float2 v1 = make_float2(acc[mf][nf][2], acc[mf][nf][3]);
            if (EPI == 4) {
                __half* Ch = (__half*)C;
                *(__half2*)(Ch + (size_t)row0 * ldc + n) = __floats2half2_rn(v0.x, v0.y);
                *(__half2*)(Ch + (size_t)(row0 + 8) * ldc + n) = __floats2half2_rn(v1.x, v1.y);
                continue;
            }
            float* C0 = C + (size_t)row0 * ldc;
            float* C1 = C0 + (size_t)8 * ldc;
            if (EPI == 1) {
                float2 o0 = *(float2*)(C0 + n);
                float2 o1 = *(float2*)(C1 + n);
                v0.x += o0.x; v0.y += o0.y;
                v1.x += o1.x; v1.y += o1.y;
            }
            if (EPI == 2) {
                float b0 = bias[n], b1 = bias[n + 1];
                v0.x += b0; v0.y += b1; v1.x += b0; v1.y += b1;
                v0.x = (v0.x > 20.f) ? v0.x : __logf(1.f + __expf(v0.x));
                v0.y = (v0.y > 20.f) ? v0.y : __logf(1.f + __expf(v0.y));
                v1.x = (v1.x > 20.f) ? v1.x : __logf(1.f + __expf(v1.x));
                v1.y = (v1.y > 20.f) ? v1.y : __logf(1.f + __expf(v1.y));
            }
            *(float2*)(C0 + n) = v0;
            *(float2*)(C1 + n) = v1;
        }
    }
}

// split-K reduce (per sequence, float4-vectorized): dbc (fp32) + delta_r (fp16)
__global__ void __launch_bounds__(256) xp_reduce(const float* __restrict__ part,
                                                 float* __restrict__ dbc,
                                                 __half* __restrict__ dr16) {
    int i = blockIdx.x * 256 + threadIdx.x;   // over HM*128/4 vec4 units
    if (i >= HM * 128 / 4) return;
    int m = i >> 5;            // 32 vec4 per row
    int col = (i & 31) * 4;
    float4 s = ((const float4*)part)[i];
#pragma unroll
    for (int z = 1; z < XPSPLIT; z++) {
        float4 v = ((const float4*)(part + (size_t)z * (HM * 128)))[i];
        s.x += v.x; s.y += v.y; s.z += v.z; s.w += v.w;
    }
    if (col < DX) *(float4*)(dbc + m * DX + col) = s;
    if (col < DR) {
        __half2 a = __floats2half2_rn(s.x, s.y);
        __half2 b = __floats2half2_rn(s.z, s.w);
        uint32_t pa = *(uint32_t*)&a, pb = *(uint32_t*)&b;
        uint2 o = make_uint2(pa, pb);
        *(uint2*)(dr16 + m * DR + col) = o;
    }
}

// ================= conversion kernels =================
__device__ __forceinline__ void cvt8(const float4* sp, uint4* dp) {
    float4 a = sp[0], b = sp[1];
    __half2 h0 = __floats2half2_rn(a.x, a.y);
    __half2 h1 = __floats2half2_rn(a.z, a.w);
    __half2 h2 = __floats2half2_rn(b.x, b.y);
    __half2 h3 = __floats2half2_rn(b.z, b.w);
    uint4 o;
    o.x = *(uint32_t*)&h0; o.y = *(uint32_t*)&h1;
    o.z = *(uint32_t*)&h2; o.w = *(uint32_t*)&h3;
    *dp = o;
}

__global__ void __launch_bounds__(256) f16cvt(const float* __restrict__ s,
                                              __half* __restrict__ d, int n8) {
    int i = blockIdx.x * 256 + threadIdx.x;
    if (i >= n8) return;
    cvt8((const float4*)s + 2 * i, (uint4*)d + i);
}

// merged layer-0 weight conversion (in_proj | dt_proj | out_proj slices)
#define C0A ((int)(IN_L / 8))
#define C0B ((int)(DT_L / 8))
#define C0C ((int)(OUT_L / 8))
__global__ void __launch_bounds__(256) convert_wts0(const float* __restrict__ s1, __half* __restrict__ d1,
                                                    const float* __restrict__ s2, __half* __restrict__ d2,
                                                    const float* __restrict__ s3, __half* __restrict__ d3) {
    int i = blockIdx.x * 256 + threadIdx.x;
    if (i >= C0A + C0B + C0C) return;
    const float* s; __half* d; int j;
    if (i < C0A)            { s = s1; d = d1; j = i; }
    else if (i < C0A + C0B) { s = s2; d = d2; j = i - C0A; }
    else                    { s = s3; d = d3; j = i - C0A - C0B; }
    cvt8((const float4*)s + 2 * j, (uint4*)d + j);
}

__global__ void __launch_bounds__(256) xpw_to_f16_v8(const float* __restrict__ s,
                                                     __half* __restrict__ d) {
    int i = blockIdx.x * 256 + threadIdx.x;
    if (i >= NLAYER * DX * ED / 8) return;
    int l = i / (DX * ED / 8);
    int rem = i % (DX * ED / 8);
    int r = rem / (ED / 8);
    int cv = rem % (ED / 8);
    cvt8((const float4*)(s + ((size_t)(l * DX + r) * ED)) + 2 * cv,
         (uint4*)(d + ((size_t)l * 128 + r) * ED) + cv);
}

__global__ void __launch_bounds__(256) embed_kernel(const int* __restrict__ tok,
                                                    const float* __restrict__ emb,
                                                    float* __restrict__ out) {
    int idx = blockIdx.x * 256 + threadIdx.x;
    int m = idx >> 8;
    int d4 = idx & 255;
    ((float4*)out)[idx] = ((const float4*)(emb + (size_t)tok[m] * Dd))[d4];
}

__global__ void __launch_bounds__(256) rmsnorm_kernel(const float* __restrict__ x,
                                                      const float* __restrict__ w,
                                                      __half* __restrict__ out) {
    int row = blockIdx.x;
    const float* xr = x + (size_t)row * Dd;
    float v[4];
    float s = 0.f;
#pragma unroll
    for (int i = 0; i < 4; i++) {
        v[i] = xr[threadIdx.x + i * 256];
        s += v[i] * v[i];
    }
#pragma unroll
    for (int o = 16; o; o >>= 1) s += __shfl_xor_sync(0xffffffffu, s, o);
    __shared__ float ss[8];
    if ((threadIdx.x & 31) == 0) ss[threadIdx.x >> 5] = s;
    __syncthreads();
    if (threadIdx.x < 32) {
        float t = (threadIdx.x < 8) ? ss[threadIdx.x] : 0.f;
#pragma unroll
        for (int o = 4; o; o >>= 1) t += __shfl_xor_sync(0xffffffffu, t, o);
        if (threadIdx.x == 0) ss[0] = t;
    }
    __syncthreads();
    float r = rsqrtf(ss[0] * (1.f / (float)Dd) + 1e-5f);
    __half* orow = out + (size_t)row * Dd;
#pragma unroll
    for (int i = 0; i < 4; i++) {
        int d = threadIdx.x + i * 256;
        orow[d] = __float2half(v[i] * r * w[d]);
    }
}

// depthwise causal conv + bias + silu (per sequence), 4 tokens per thread
// sliding-window: 7 taps serve 4 outputs; per-output accumulation order is
// identical to the reference (adding w*0.0 for out-of-range taps is exact).
__global__ void __launch_bounds__(256) conv_silu_kernel(const __half* __restrict__ xz,
                                                        const float* __restrict__ cw,
                                                        const float* __restrict__ cb,
                                                        __half* __restrict__ xs16) {
    int idx = blockIdx.x * 256 + threadIdx.x;   // over (HM/4)*(ED/2)
    if (idx >= (HM / 4) * (ED / 2)) return;
    int e2 = idx & (ED / 2 - 1);
    int e = e2 * 2;
    int m0 = (idx >> 10) * 4;                   // ED/2 = 1024
    float4 wa = *(const float4*)(cw + e * 4);
    float4 wb = *(const float4*)(cw + e * 4 + 4);
    float2 cbv = *(const float2*)(cb + e);

    float2 xw[7];                                // tokens m0-3 .. m0+3
#pragma unroll
    for (int k = 0; k < 7; k++) {
        int m = m0 - 3 + k;
        if (m >= 0)
            xw[k] = __half22float2(*(const __half2*)(xz + (size_t)m * (2 * ED) + e));
        else
            xw[k] = make_float2(0.f, 0.f);
    }
#pragma unroll
    for (int k = 0; k < 4; k++) {
        // token m = m0+k uses taps xw[k+3](m), xw[k+2](m-1), xw[k+1](m-2), xw[k](m-3)
        float a0 = cbv.x + wa.w * xw[k + 3].x;
        float a1 = cbv.y + wb.w * xw[k + 3].y;
        a0 += wa.z * xw[k + 2].x; a1 += wb.z * xw[k + 2].y;
        a0 += wa.y * xw[k + 1].x; a1 += wb.y * xw[k + 1].y;
        a0 += wa.x * xw[k].x;     a1 += wb.x * xw[k].y;
        float r0 = a0 / (1.f + __expf(-a0));
        float r1 = a1 / (1.f + __expf(-a1));
        *(__half2*)(xs16 + (size_t)(m0 + k) * ED + e) = __floats2half2_rn(r0, r1);
    }
}

// ================= chunked selective scan (4 lanes x 4 states, 32 chunks) ========
__global__ void __launch_bounds__(256) scan_pass1(const float* __restrict__ delta,
                                                  const __half* __restrict__ xs,
                                                  const float* __restrict__ dbc,
                                                  const float* __restrict__ A_log,
                                                  int bsel) {
    int u = blockIdx.x * 64 + (threadIdx.x >> 2);   // 0 .. ED*CHUNKS-1
    int j = threadIdx.x & 3;                        // states 4j..4j+3
    int c = u >> 11;
    int e = u & (ED - 1);
    float4 al = *(const float4*)(A_log + e * Nn + 4 * j);
    float a0 = -__expf(al.x) * 1.44269504f;
    float a1 = -__expf(al.y) * 1.44269504f;
    float a2 = -__expf(al.z) * 1.44269504f;
    float a3 = -__expf(al.w) * 1.44269504f;
    size_t t0 = (size_t)bsel * Ll + c * CLEN;
    const float* pd = delta + t0 * ED + e;
    const __half* pxs = xs + t0 * ED + e;
    const float* pB = dbc + t0 * DX + DR + 4 * j;
    float h0 = 0.f, h1 = 0.f, h2 = 0.f, h3 = 0.f;
    float s0 = 0.f, s1 = 0.f, s2 = 0.f, s3 = 0.f;
#pragma unroll 8
    for (int t = 0; t < CLEN; t++) {
        float d = *pd;
        float xv = __half2float(*pxs);
        float4 Bv = *(const float4*)pB;
        float e0 = d * a0, e1 = d * a1, e2v = d * a2, e3 = d * a3;
        s0 += e0; s1 += e1; s2 += e2v; s3 += e3;
        float dx = d * xv;
        h0 = fmaf(exp2f(e0), h0, dx * Bv.x);
        h1 = fmaf(exp2f(e1), h1, dx * Bv.y);
        h2 = fmaf(exp2f(e2v), h2, dx * Bv.z);
        h3 = fmaf(exp2f(e3), h3, dx * Bv.w);
        pd += ED; pxs += ED; pB += DX;
    }
    int o = (((bsel * ED + e) * CHUNKS) + c) * Nn + 4 * j;
    *(float4*)(g_hl + o) = make_float4(h0, h1, h2, h3);
    *(float4*)(g_A + o) = make_float4(exp2f(s0), exp2f(s1), exp2f(s2), exp2f(s3));
}

// pass2: serial prefix over chunks -> start state per chunk (per sequence)
__global__ void __launch_bounds__(256) scan_pass2(int bsel) {
    int i = blockIdx.x * 256 + threadIdx.x;   // 0 .. ED*Nn-1
    int e = i >> 4, n = i & 15;
    int chb = (bsel * ED + e) * CHUNKS;
    float hs = 0.f;
#pragma unroll
    for (int c = 0; c < CHUNKS; c++) {
        int o = (chb + c) * Nn + n;
        g_hs[o] = hs;
        hs = fmaf(g_A[o], hs, g_hl[o]);
    }
}

__global__ void __launch_bounds__(256) scan_pass3(const float* __restrict__ delta,
                                                  const __half* __restrict__ xs,
                                                  const float* __restrict__ dbc,
                                                  const __half* __restrict__ xz,
                                                  const float* __restrict__ A_log,
                                                  const float* __restrict__ Dp,
                                                  __half* __restrict__ y,
                                                  int bsel) {
    int u = blockIdx.x * 64 + (threadIdx.x >> 2);
    int j = threadIdx.x & 3;
    int c = u >> 11;
    int e = u & (ED - 1);
    float4 al = *(const float4*)(A_log + e * Nn + 4 * j);
    float a0 = -__expf(al.x) * 1.44269504f;
    float a1 = -__expf(al.y) * 1.44269504f;
    float a2 = -__expf(al.z) * 1.44269504f;
    float a3 = -__expf(al.w) * 1.44269504f;
    float dpar = Dp[e];

    int o = (((bsel * ED + e) * CHUNKS) + c) * Nn + 4 * j;
    float4 Hs = *(const float4*)(g_hs + o);
    float h0 = Hs.x, h1 = Hs.y, h2 = Hs.z, h3 = Hs.w;

    size_t t0 = (size_t)bsel * Ll + c * CLEN;
    const float* pd = delta + t0 * ED + e;
    const __half* pxs = xs + t0 * ED + e;
    const float* pB = dbc + t0 * DX + DR + 4 * j;
    const float* pC = dbc + t0 * DX + DR + Nn + 4 * j;
    const __half* pz = xz + t0 * (2 * ED) + ED + e;
    __half* py = y + t0 * ED + e;

#pragma unroll 8
    for (int t = 0; t < CLEN; t++) {
        float d = *pd;
        float xv = __half2float(*pxs);
        float4 Bv = *(const float4*)pB;
        float4 Cv = *(const float4*)pC;
        float dx = d * xv;
        h0 = fmaf(exp2f(d * a0), h0, dx * Bv.x);
        h1 = fmaf(exp2f(d * a1), h1, dx * Bv.y);
        h2 = fmaf(exp2f(d * a2), h2, dx * Bv.z);
        h3 = fmaf(exp2f(d * a3), h3, dx * Bv.w);
        float p = h0 * Cv.x + h1 * Cv.y + h2 * Cv.z + h3 * Cv.w;
        p += __shfl_xor_sync(0xffffffffu, p, 1);
        p += __shfl_xor_sync(0xffffffffu, p, 2);
        if (j == 0) {
            float z = __half2float(*pz);
            float sz = z / (1.f + __expf(-z));
            py[0] = __float2half((p + dpar * xv) * sz);
        }
        pd += ED; pxs += ED; pB += DX; pC += DX; pz += 2 * ED; py += ED;
    }
}

// ---------------- host side ----------------
static void launch_hgemm(int epi, cudaStream_t st,
                         const __half* A, int lda, const __half* B, int ldb,
                         float* C, int ldc, int M, int N, int Nstore, int K,
                         const float* bias, int zsplit, size_t zstrC) {
    dim3 grid(N / BNt, M / BMt, zsplit);
    if (epi == 0)
        hgemm_mma<0><<<grid, GTHREADS, GEMM_SMEM, st>>>(A, lda, B, ldb, C, ldc, M, N, Nstore, K, bias, zstrC);
    else if (epi == 1)
        hgemm_mma<1><<<grid, GTHREADS, GEMM_SMEM, st>>>(A, lda, B, ldb, C, ldc, M, N, Nstore, K, bias, zstrC);
    else if (epi == 2)
        hgemm_mma<2><<<grid, GTHREADS, GEMM_SMEM, st>>>(A, lda, B, ldb, C, ldc, M, N, Nstore, K, bias, zstrC);
    else
        hgemm_mma<4><<<grid, GTHREADS, GEMM_SMEM, st>>>(A, lda, B, ldb, C, ldc, M, N, Nstore, K, bias, zstrC);
}

static void launch_cvt(const float* s, __half* d, size_t elems, cudaStream_t st) {
    int n8 = (int)(elems / 8);
    f16cvt<<<(n8 + 255) / 256, 256, 0, st>>>(s, d, n8);
}

extern "C" void kernel_launch(void* const* d_in, const int* in_sizes, int n_in,
                              void* d_out, int out_size) {
    const int* tokens = (const int*)d_in[0];
    const float* embedding = (const float*)d_in[1];
    const float* in_proj_w = (const float*)d_in[2];
    const float* conv_w = (const float*)d_in[3];
    const float* conv_b = (const float*)d_in[4];
    const float* x_proj_w = (const float*)d_in[5];
    const float* dt_proj_w = (const float*)d_in[6];
    const float* dt_proj_b = (const float*)d_in[7];
    const float* A_log = (const float*)d_in[8];
    const float* D_param = (const float*)d_in[9];
    const float* out_proj_w = (const float*)d_in[10];
    const float* norm_w = (const float*)d_in[11];
    const float* norm_f_w = (const float*)d_in[12];
    float* logits = (float*)d_out;

    float *px, *pdelta, *pdbc, *pxpp;
    __half *pxz16, *pxn16, *pxs16, *pdr16, *py16, *pwin, *pwxp, *pwdt, *pwout, *pemb;
    cudaGetSymbolAddress((void**)&px, g_x);
    cudaGetSymbolAddress((void**)&pdelta, g_delta);
    cudaGetSymbolAddress((void**)&pdbc, g_dbc);
    cudaGetSymbolAddress((void**)&pxpp, g_xp_part);
    cudaGetSymbolAddress((void**)&pxz16, h_xz);
    cudaGetSymbolAddress((void**)&pxn16, h_xn);
    cudaGetSymbolAddress((void**)&pxs16, h_xs);
    cudaGetSymbolAddress((void**)&pdr16, h_dr);
    cudaGetSymbolAddress((void**)&py16, h_y);
    cudaGetSymbolAddress((void**)&pwin, h_w_in);
    cudaGetSymbolAddress((void**)&pwxp, h_w_xp);
    cudaGetSymbolAddress((void**)&pwdt, h_w_dt);
    cudaGetSymbolAddress((void**)&pwout, h_w_out);
    cudaGetSymbolAddress((void**)&pemb, h_emb);

    // one-time smem attribute setup + side streams/events
    static cudaStream_t s2 = nullptr, s3 = nullptr;
    static cudaEvent_t evFork = nullptr, evJoin = nullptr, evEmb = nullptr, evW = nullptr;
    static cudaEvent_t evXpw = nullptr;
    static int sinit = 0;
    if (!sinit) {
        cudaFuncSetAttribute(hgemm_mma<0>, cudaFuncAttributeMaxDynamicSharedMemorySize, GEMM_SMEM);
        cudaFuncSetAttribute(hgemm_mma<1>, cudaFuncAttributeMaxDynamicSharedMemorySize, GEMM_SMEM);
        cudaFuncSetAttribute(hgemm_mma<2>, cudaFuncAttributeMaxDynamicSharedMemorySize, GEMM_SMEM);
        cudaFuncSetAttribute(hgemm_mma<4>, cudaFuncAttributeMaxDynamicSharedMemorySize, GEMM_SMEM);
        bool ok = cudaStreamCreateWithFlags(&s2, cudaStreamNonBlocking) == cudaSuccess &&
                  cudaStreamCreateWithFlags(&s3, cudaStreamNonBlocking) == cudaSuccess &&
                  cudaEventCreateWithFlags(&evFork, cudaEventDisableTiming) == cudaSuccess &&
                  cudaEventCreateWithFlags(&evJoin, cudaEventDisableTiming) == cudaSuccess &&
                  cudaEventCreateWithFlags(&evEmb, cudaEventDisableTiming) == cudaSuccess &&
                  cudaEventCreateWithFlags(&evXpw, cudaEventDisableTiming) == cudaSuccess &&
                  cudaEventCreateWithFlags(&evW, cudaEventDisableTiming) == cudaSuccess;
        sinit = ok ? 1 : -1;
    }
    bool dual = (sinit == 1);

    // critical-path conversions: layer-0 slices in ONE kernel
    convert_wts0<<<(C0A + C0B + C0C + 255) / 256, 256>>>(in_proj_w, pwin,
                                                         dt_proj_w, pwdt,
                                                         out_proj_w, pwout);
    embed_kernel<<<(Mm * Dd / 4) / 256, 256>>>(tokens, embedding, px);

    if (dual) {
        cudaEventRecord(evFork, 0);
        cudaStreamWaitEvent(s2, evFork, 0);
        cudaStreamWaitEvent(s3, evFork, 0);
        // deferred work on s3: xpw first (needed by layer-0 x_proj, ~150us in),
        // then layers 1..3 weights, then embedding table
        xpw_to_f16_v8<<<(NLAYER * DX * ED / 8 + 255) / 256, 256, 0, s3>>>(x_proj_w, pwxp);
        cudaEventRecord(evXpw, s3);
        launch_cvt(in_proj_w + IN_L, pwin + IN_L, (NLAYER - 1) * IN_L, s3);
        launch_cvt(dt_proj_w + DT_L, pwdt + DT_L, (NLAYER - 1) * DT_L, s3);
        launch_cvt(out_proj_w + OUT_L, pwout + OUT_L, (NLAYER - 1) * OUT_L, s3);
        cudaEventRecord(evW, s3);
        launch_cvt(embedding, pemb, (size_t)Vv * Dd, s3);
        cudaEventRecord(evEmb, s3);
    } else {
        xpw_to_f16_v8<<<(NLAYER * DX * ED / 8 + 255) / 256, 256>>>(x_proj_w, pwxp);
        launch_cvt(in_proj_w + IN_L, pwin + IN_L, (NLAYER - 1) * IN_L, 0);
        launch_cvt(dt_proj_w + DT_L, pwdt + DT_L, (NLAYER - 1) * DT_L, 0);
        launch_cvt(out_proj_w + OUT_L, pwout + OUT_L, (NLAYER - 1) * OUT_L, 0);
        launch_cvt(embedding, pemb, (size_t)Vv * Dd, 0);
    }

    for (int l = 0; l < NLAYER; l++) {
        if (dual && l == 1) {   // layers >=1 need the deferred weight conversions
            cudaStreamWaitEvent(0, evW, 0);
            cudaStreamWaitEvent(s2, evW, 0);
        }
        for (int b = 0; b < Bb; b++) {
            cudaStream_t sb = (dual && b == 1) ? s2 : (cudaStream_t)0;
            size_t off = (size_t)b * HM;
            rmsnorm_kernel<<<HM, 256, 0, sb>>>(px + off * Dd, norm_w + (size_t)l * Dd,
                                               pxn16 + off * Dd);
            launch_hgemm(4, sb, pxn16 + off * Dd, Dd, pwin + (size_t)l * IN_L, Dd,
                         (float*)(pxz16 + off * 2 * ED), 2 * ED, HM, 2 * ED, 2 * ED, Dd,
                         nullptr, 1, 0);
            conv_silu_kernel<<<((HM / 4) * (ED / 2) + 255) / 256, 256, 0, sb>>>(
                pxz16 + off * 2 * ED, conv_w + (size_t)l * ED * DCONV,
                conv_b + (size_t)l * ED, pxs16 + off * ED);
            if (dual && l == 0)
                cudaStreamWaitEvent(sb, evXpw, 0);   // xpw fp16 ready
            float* partb = pxpp + (size_t)b * XPSPLIT * HM * 128;
            launch_hgemm(0, sb, pxs16 + off * ED, ED, pwxp + (size_t)l * 128 * ED, ED,
                         partb, 128, HM, 128, 128, ED / XPSPLIT, nullptr,
                         XPSPLIT, (size_t)HM * 128);
            xp_reduce<<<(HM * 128 / 4 + 255) / 256, 256, 0, sb>>>(partb, pdbc + off * DX,
                                                                  pdr16 + off * DR);
            launch_hgemm(2, sb, pdr16 + off * DR, DR, pwdt + (size_t)l * DT_L, DR,
                         pdelta + off * ED, ED, HM, ED, ED, DR,
                         dt_proj_b + (size_t)l * ED, 1, 0);
            scan_pass1<<<(ED * CHUNKS) / 64, 256, 0, sb>>>(
                pdelta, pxs16, pdbc, A_log + (size_t)l * ED * Nn, b);
            scan_pass2<<<(ED * Nn) / 256, 256, 0, sb>>>(b);
            scan_pass3<<<(ED * CHUNKS) / 64, 256, 0, sb>>>(
                pdelta, pxs16, pdbc, pxz16, A_log + (size_t)l * ED * Nn,
                D_param + (size_t)l * ED, py16, b);
            launch_hgemm(1, sb, py16 + off * ED, ED, pwout + (size_t)l * OUT_L, ED,
                         px + off * Dd, Dd, HM, Dd, Dd, ED, nullptr, 1, 0);
        }
    }

    // per-sequence final rmsnorm + logits half-GEMM on each sequence's stream.
    if (dual) {
        cudaStreamWaitEvent(0, evEmb, 0);
        cudaStreamWaitEvent(s2, evEmb, 0);
        for (int b = 0; b < Bb; b++) {
            cudaStream_t sb = (b == 1) ? s2 : (cudaStream_t)0;
            size_t off = (size_t)b * HM;
            rmsnorm_kernel<<<HM, 256, 0, sb>>>(px + off * Dd, norm_f_w, pxn16 + off * Dd);
            launch_hgemm(0, sb, pxn16 + off * Dd, Dd, pemb, Dd,
                         logits + off * Vv, Vv, HM, Vv, Vv, Dd, nullptr, 1, 0);
        }
        cudaEventRecord(evJoin, s2);
        cudaStreamWaitEvent(0, evJoin, 0);
    } else {
        rmsnorm_kernel<<<Mm, 256>>>(px, norm_f_w, pxn16);
        launch_hgemm(0, (cudaStream_t)0, pxn16, Dd, pemb, Dd, logits, Vv, Mm, Vv, Vv, Dd,
                     nullptr, 1, 0);
    }
}